// round 2
// baseline (speedup 1.0000x reference)
#include <cuda_runtime.h>
#include <cuda_fp16.h>
#include <cstdint>

#define DIMZ 64
#define HID 256
#define NBATCH 32768
#define NSTEPS 100
#define TILE_M 128
#define NTILES 256
#define NTHREADS 256
#define DT_F 0.01f

// tcgen05 is an sm_103a arch-specific feature: only emit it in the
// arch-specific compilation pass. Generic compute_103 passes get an
// empty kernel body (never executed at runtime on GB300 — the sm_103a
// cubin takes precedence in the fatbin).
#if defined(__CUDA_ARCH__)
#if defined(__CUDA_ARCH_FEAT_SM103_ALL) || \
    (defined(__CUDA_ARCH_SPECIFIC__) && (__CUDA_ARCH_SPECIFIC__ == 1030)) || \
    (defined(__CUDA_ARCH_HAS_FEATURE__) && defined(__CUDA_ARCH_FEAT_SM101_ALL))
#define CNF_HAS_TCGEN05 1
#else
#define CNF_HAS_TCGEN05 0
#endif
#else
#define CNF_HAS_TCGEN05 0
#endif

// ---- TMEM column layout (512 f32 cols) ----
#define TM_D12 0u      // 256 cols: f32 D for GEMM1 (N=256) and GEMM2 (N=256)
#define TM_D3 256u     // 64 cols:  f32 D for GEMM3 (N=64)
#define TM_AH 320u     // 128 cols: H activations f16 packed (K=256)
#define TM_AZ 448u     // 32 cols:  z input f16 packed (K=64)
#define TMEM_NCOLS 512u

// ---- SMEM byte layout ----
#define SM_TMEMPTR 0
#define SM_MBAR 8
#define SM_B1H 16       // 128 x u32 (half2 bias1)
#define SM_B2H 528      // 128 x u32 (half2 bias2)
#define SM_B3F 1040     // 64 x f32 bias3
#define SM_W1 2048      // [256 n][64 k] f16, 128B rows, SW128  (32 KB)
#define SM_W2 34816     // [256 n][256 k] f16 blocked atoms     (128 KB)
#define SM_W3 165888    // [64 n][256 k] f16 blocked atoms      (32 KB)
#define SM_TOTAL 198656

// idesc kind::f16: dtype=F32(1<<4), atype=btype=F16(0), N/8<<17, M/16<<24
#define IDESC_N256 0x08400010u
#define IDESC_N64 0x08100010u

// SW128 K-major smem descriptor base: layout=2, version=1, SBO=64, LBO=1
static constexpr uint64_t DESC_BASE_SW128 =
    (uint64_t(2) << 61) | (uint64_t(1) << 46) | (uint64_t(64) << 32) | (uint64_t(1) << 16);

#if CNF_HAS_TCGEN05

__device__ __forceinline__ uint32_t smem_u32(const void* p) {
    uint32_t a;
    asm("{ .reg .u64 t; cvta.to.shared.u64 t, %1; cvt.u32.u64 %0, t; }" : "=r"(a) : "l"(p));
    return a;
}
__device__ __forceinline__ uint32_t elect1() {
    uint32_t r;
    asm volatile("{ .reg .pred p; elect.sync _|p, 0xFFFFFFFF; selp.b32 %0, 1, 0, p; }" : "=r"(r));
    return r;
}
__device__ __forceinline__ uint32_t swz128(uint32_t x) { return x ^ ((x >> 3) & 0x70); }

__device__ __forceinline__ uint32_t pack_f16x2(float lo, float hi) {
    uint32_t d;
    asm("cvt.rn.f16x2.f32 %0, %1, %2;" : "=r"(d) : "f"(hi), "f"(lo));
    return d;
}
__device__ __forceinline__ uint32_t hadd2u(uint32_t a, uint32_t b) {
    uint32_t d;
    asm("add.rn.f16x2 %0, %1, %2;" : "=r"(d) : "r"(a), "r"(b));
    return d;
}
__device__ __forceinline__ uint32_t htanh2(uint32_t a) {
    uint32_t d;
    asm("tanh.approx.f16x2 %0, %1;" : "=r"(d) : "r"(a));
    return d;
}

#define TCGEN05_ALLOC(smem_addr, nCols) \
    asm volatile("tcgen05.alloc.cta_group::1.sync.aligned.shared::cta.b32 [%0], %1;" \
                 :: "r"((uint32_t)(smem_addr)), "r"((uint32_t)(nCols)) : "memory")
#define TCGEN05_DEALLOC(tmem_addr, nCols) \
    asm volatile("tcgen05.dealloc.cta_group::1.sync.aligned.b32 %0, %1;" \
                 :: "r"(tmem_addr), "r"((uint32_t)(nCols)))
#define TCGEN05_WAIT_LD() asm volatile("tcgen05.wait::ld.sync.aligned;" ::: "memory")
#define TCGEN05_WAIT_ST() asm volatile("tcgen05.wait::st.sync.aligned;" ::: "memory")
#define TCGEN05_FENCE_BEFORE() asm volatile("tcgen05.fence::before_thread_sync;" ::: "memory")
#define TCGEN05_FENCE_AFTER() asm volatile("tcgen05.fence::after_thread_sync;" ::: "memory")
#define TCGEN05_COMMIT(mbar) \
    asm volatile("tcgen05.commit.cta_group::1.mbarrier::arrive::one.shared::cluster.b64 [%0];" \
                 :: "r"((uint32_t)(mbar)) : "memory")
#define MBARRIER_INIT(mbar, count) \
    asm volatile("mbarrier.init.shared.b64 [%0], %1;" \
                 :: "r"((uint32_t)(mbar)), "r"((uint32_t)(count)) : "memory")

#define MBARRIER_WAIT_PARITY(mbar_smem_addr, phase_parity) do { \
    uint32_t _mbar = (uint32_t)(mbar_smem_addr); \
    uint32_t _parity = (uint32_t)(phase_parity); \
    uint32_t _done; \
    asm volatile( \
        "{\n\t" \
        ".reg .pred p;\n\t" \
        "mbarrier.try_wait.parity.acquire.cta.shared::cta.b64 p, [%1], %2;\n\t" \
        "selp.b32 %0, 1, 0, p;\n\t" \
        "}" \
        : "=r"(_done) : "r"(_mbar), "r"(_parity) : "memory"); \
    if (!_done) { \
        asm volatile( \
            "{\n\t" \
            ".reg .pred P1;\n\t" \
            "WAIT_LOOP_%=:\n\t" \
            "mbarrier.try_wait.parity.acquire.cta.shared::cta.b64 P1, [%0], %1, 0x989680;\n\t" \
            "@P1 bra.uni WAIT_DONE_%=;\n\t" \
            "bra.uni WAIT_LOOP_%=;\n\t" \
            "WAIT_DONE_%=:\n\t" \
            "}" \
            :: "r"(_mbar), "r"(_parity) : "memory"); \
    } \
} while (0)

#define TCGEN05_LD_32X32B_X32(r, tmem_addr) \
    asm volatile( \
        "tcgen05.ld.sync.aligned.32x32b.x32.b32 " \
        "{%0, %1, %2, %3, %4, %5, %6, %7, " \
        " %8, %9, %10, %11, %12, %13, %14, %15, " \
        " %16, %17, %18, %19, %20, %21, %22, %23, " \
        " %24, %25, %26, %27, %28, %29, %30, %31}, [%32];" \
        : "=r"((r)[0]),  "=r"((r)[1]),  "=r"((r)[2]),  "=r"((r)[3]), \
          "=r"((r)[4]),  "=r"((r)[5]),  "=r"((r)[6]),  "=r"((r)[7]), \
          "=r"((r)[8]),  "=r"((r)[9]),  "=r"((r)[10]), "=r"((r)[11]), \
          "=r"((r)[12]), "=r"((r)[13]), "=r"((r)[14]), "=r"((r)[15]), \
          "=r"((r)[16]), "=r"((r)[17]), "=r"((r)[18]), "=r"((r)[19]), \
          "=r"((r)[20]), "=r"((r)[21]), "=r"((r)[22]), "=r"((r)[23]), \
          "=r"((r)[24]), "=r"((r)[25]), "=r"((r)[26]), "=r"((r)[27]), \
          "=r"((r)[28]), "=r"((r)[29]), "=r"((r)[30]), "=r"((r)[31]) \
        : "r"(tmem_addr))

#define TCGEN05_ST_32X32B_X16(tmem_addr, r) \
    asm volatile( \
        "tcgen05.st.sync.aligned.32x32b.x16.b32 [%0], " \
        "{%1, %2, %3, %4, %5, %6, %7, %8, " \
        " %9, %10, %11, %12, %13, %14, %15, %16};" \
        :: "r"(tmem_addr), \
           "r"((r)[0]),  "r"((r)[1]),  "r"((r)[2]),  "r"((r)[3]), \
           "r"((r)[4]),  "r"((r)[5]),  "r"((r)[6]),  "r"((r)[7]), \
           "r"((r)[8]),  "r"((r)[9]),  "r"((r)[10]), "r"((r)[11]), \
           "r"((r)[12]), "r"((r)[13]), "r"((r)[14]), "r"((r)[15]) \
        : "memory")

__device__ __forceinline__ void mma_f16_ts(uint32_t d, uint32_t a, uint64_t bdesc,
                                           uint32_t idesc, uint32_t accum) {
    asm volatile(
        "{\n\t"
        ".reg .pred p;\n\t"
        "setp.ne.u32 p, %5, 0;\n\t"
        "tcgen05.mma.cta_group::1.kind::f16 [%0], [%1], %2, %3, {%4, %4, %4, %4}, p;\n\t"
        "}"
        :: "r"(d), "r"(a), "l"(bdesc), "r"(idesc), "r"(0u), "r"(accum)
        : "memory");
}

// Epilogue for hidden layers: D12 cols -> +bias -> tanh(f16x2) -> A_h
__device__ __forceinline__ void epilogue_hidden(uint32_t tb, const char* smem, int biasOff,
                                                int wg, uint32_t warpoff) {
    const uint32_t* bh = (const uint32_t*)(smem + biasOff);
#pragma unroll
    for (int c = 0; c < 4; c++) {
        uint32_t c0 = (uint32_t)(wg * 128 + c * 32);
        uint32_t r[32];
        TCGEN05_LD_32X32B_X32(r, tb + TM_D12 + c0 + warpoff);
        TCGEN05_WAIT_LD();
        uint32_t o[16];
#pragma unroll
        for (int j = 0; j < 16; j++) {
            uint32_t p = pack_f16x2(__uint_as_float(r[2 * j]), __uint_as_float(r[2 * j + 1]));
            o[j] = htanh2(hadd2u(p, bh[(c0 >> 1) + j]));
        }
        TCGEN05_ST_32X32B_X16(tb + TM_AH + (c0 >> 1) + warpoff, o);
    }
    TCGEN05_WAIT_ST();
}

#endif  // CNF_HAS_TCGEN05

extern "C" __global__ void __launch_bounds__(NTHREADS, 1)
cnf_rk4_kernel(const float* __restrict__ z0,
               const float* __restrict__ W1, const float* __restrict__ b1,
               const float* __restrict__ W2, const float* __restrict__ b2,
               const float* __restrict__ W3, const float* __restrict__ b3,
               float* __restrict__ out) {
#if CNF_HAS_TCGEN05
    extern __shared__ char smem[];
    const uint32_t sb = smem_u32(smem);
    const int tid = threadIdx.x;
    const int w = tid >> 5;
    const int lane = tid & 31;
    const int sp = w & 3;        // TMEM subpartition (SMSP)
    const int wg = w >> 2;       // warpgroup (0/1): column-half split
    const uint32_t warpoff = (uint32_t)sp << 21;

    if (w == 0) TCGEN05_ALLOC(sb + SM_TMEMPTR, TMEM_NCOLS);

    // ---- Convert weights to f16 B-operand layouts in SMEM ----
    // W1: global [64 k][256 n] -> B1[n][k], 128B rows, SW128
    for (int i = tid; i < 64 * 256; i += NTHREADS) {
        int k = i >> 8, n = i & 255;
        *(__half*)(smem + SM_W1 + swz128((uint32_t)(n * 128 + k * 2))) = __float2half_rn(W1[i]);
    }
    // W2: global [256 k][256 n] -> blocked atoms: 32 atom-rows x 4 atom-cols
    for (int i = tid; i < 256 * 256; i += NTHREADS) {
        int k = i >> 8, n = i & 255;
        uint32_t off = (uint32_t)((((n >> 3) + (k >> 6) * 32) << 10) + ((n & 7) << 7) + ((k & 63) << 1));
        *(__half*)(smem + SM_W2 + swz128(off)) = __float2half_rn(W2[i]);
    }
    // W3: global [256 k][64 n] -> blocked atoms: 8 atom-rows x 4 atom-cols
    for (int i = tid; i < 256 * 64; i += NTHREADS) {
        int k = i >> 6, n = i & 63;
        uint32_t off = (uint32_t)((((n >> 3) + (k >> 6) * 8) << 10) + ((n & 7) << 7) + ((k & 63) << 1));
        *(__half*)(smem + SM_W3 + swz128(off)) = __float2half_rn(W3[i]);
    }
    // biases
    for (int i = tid; i < 128; i += NTHREADS) {
        ((uint32_t*)(smem + SM_B1H))[i] = pack_f16x2(b1[2 * i], b1[2 * i + 1]);
        ((uint32_t*)(smem + SM_B2H))[i] = pack_f16x2(b2[2 * i], b2[2 * i + 1]);
    }
    for (int i = tid; i < 64; i += NTHREADS) ((float*)(smem + SM_B3F))[i] = b3[i];

    if (tid == 0) MBARRIER_INIT(sb + SM_MBAR, 1);
    __syncthreads();

    uint32_t tb;
    asm volatile("ld.shared.b32 %0, [%1];" : "=r"(tb) : "r"(sb + SM_TMEMPTR));

    // ---- Load z tile: thread owns row (sp*32+lane), cols [wg*32, wg*32+32) ----
    const int row = blockIdx.x * TILE_M + sp * 32 + lane;
    float zc[32], acc[32];
    {
        const float4* zp = (const float4*)(z0 + (size_t)row * DIMZ + wg * 32);
#pragma unroll
        for (int q = 0; q < 8; q++) {
            float4 v = zp[q];
            zc[4 * q] = v.x; zc[4 * q + 1] = v.y; zc[4 * q + 2] = v.z; zc[4 * q + 3] = v.w;
        }
#pragma unroll
        for (int j = 0; j < 32; j++) acc[j] = 0.0f;
    }

    // initial A_z = f16(z0)
    {
        uint32_t o[16];
#pragma unroll
        for (int j = 0; j < 16; j++) o[j] = pack_f16x2(zc[2 * j], zc[2 * j + 1]);
        TCGEN05_ST_32X32B_X16(tb + TM_AZ + (uint32_t)(wg * 16) + warpoff, o);
        TCGEN05_WAIT_ST();
    }

    const uint64_t dW1 = DESC_BASE_SW128 | (((uint64_t)((sb + SM_W1) >> 4)) & 0x3FFF);
    const uint64_t dW2 = DESC_BASE_SW128 | (((uint64_t)((sb + SM_W2) >> 4)) & 0x3FFF);
    const uint64_t dW3 = DESC_BASE_SW128 | (((uint64_t)((sb + SM_W3) >> 4)) & 0x3FFF);

    uint32_t phase = 0;

    for (int it = 0; it < NSTEPS * 4; ++it) {
        const int s = it & 3;

        // ======== GEMM1: D12 = A_z @ W1^T  (M=128, N=256, K=64) ========
        TCGEN05_FENCE_BEFORE();
        __syncthreads();
        if (w == 0) {
            TCGEN05_FENCE_AFTER();
            if (elect1()) {
#pragma unroll
                for (int ks = 0; ks < 4; ks++)
                    mma_f16_ts(tb + TM_D12, tb + TM_AZ + (uint32_t)(ks * 8),
                               dW1 + (uint64_t)(ks * 2), IDESC_N256, ks > 0);
                TCGEN05_COMMIT(sb + SM_MBAR);
            }
        }
        MBARRIER_WAIT_PARITY(sb + SM_MBAR, phase);
        phase ^= 1u;
        TCGEN05_FENCE_AFTER();
        epilogue_hidden(tb, smem, SM_B1H, wg, warpoff);   // H1 -> A_h

        // ======== GEMM2: D12 = A_h @ W2^T  (M=128, N=256, K=256) ========
        TCGEN05_FENCE_BEFORE();
        __syncthreads();
        if (w == 0) {
            TCGEN05_FENCE_AFTER();
            if (elect1()) {
#pragma unroll
                for (int ks = 0; ks < 16; ks++)
                    mma_f16_ts(tb + TM_D12, tb + TM_AH + (uint32_t)(ks * 8),
                               dW2 + (uint64_t)((ks & 3) * 2 + (ks >> 2) * 2048), IDESC_N256, ks > 0);
                TCGEN05_COMMIT(sb + SM_MBAR);
            }
        }
        MBARRIER_WAIT_PARITY(sb + SM_MBAR, phase);
        phase ^= 1u;
        TCGEN05_FENCE_AFTER();
        epilogue_hidden(tb, smem, SM_B2H, wg, warpoff);   // H2 -> A_h

        // ======== GEMM3: D3 = A_h @ W3^T  (M=128, N=64, K=256) ========
        TCGEN05_FENCE_BEFORE();
        __syncthreads();
        if (w == 0) {
            TCGEN05_FENCE_AFTER();
            if (elect1()) {
#pragma unroll
                for (int ks = 0; ks < 16; ks++)
                    mma_f16_ts(tb + TM_D3, tb + TM_AH + (uint32_t)(ks * 8),
                               dW3 + (uint64_t)((ks & 3) * 2 + (ks >> 2) * 512), IDESC_N64, ks > 0);
                TCGEN05_COMMIT(sb + SM_MBAR);
            }
        }
        MBARRIER_WAIT_PARITY(sb + SM_MBAR, phase);
        phase ^= 1u;
        TCGEN05_FENCE_AFTER();

        // ======== RK4 stage epilogue: read D3 (=k), update state, write A_z ========
        {
            uint32_t r[32];
            TCGEN05_LD_32X32B_X32(r, tb + TM_D3 + (uint32_t)(wg * 32) + warpoff);
            TCGEN05_WAIT_LD();
            const float* b3s = (const float*)(smem + SM_B3F) + wg * 32;
            float zin[32];
            if (s == 0) {
#pragma unroll
                for (int j = 0; j < 32; j++) {
                    float f = __uint_as_float(r[j]) + b3s[j];
                    acc[j] = f;
                    zin[j] = fmaf(0.5f * DT_F, f, zc[j]);
                }
            } else if (s == 1) {
#pragma unroll
                for (int j = 0; j < 32; j++) {
                    float f = __uint_as_float(r[j]) + b3s[j];
                    acc[j] = fmaf(2.0f, f, acc[j]);
                    zin[j] = fmaf(0.5f * DT_F, f, zc[j]);
                }
            } else if (s == 2) {
#pragma unroll
                for (int j = 0; j < 32; j++) {
                    float f = __uint_as_float(r[j]) + b3s[j];
                    acc[j] = fmaf(2.0f, f, acc[j]);
                    zin[j] = fmaf(DT_F, f, zc[j]);
                }
            } else {
#pragma unroll
                for (int j = 0; j < 32; j++) {
                    float f = __uint_as_float(r[j]) + b3s[j];
                    acc[j] += f;
                    zc[j] = fmaf(DT_F / 6.0f, acc[j], zc[j]);
                    zin[j] = zc[j];
                }
            }
            uint32_t o[16];
#pragma unroll
            for (int j = 0; j < 16; j++) o[j] = pack_f16x2(zin[2 * j], zin[2 * j + 1]);
            TCGEN05_ST_32X32B_X16(tb + TM_AZ + (uint32_t)(wg * 16) + warpoff, o);
            TCGEN05_WAIT_ST();
        }
    }

    // ---- write result ----
    {
        float4* op = (float4*)(out + (size_t)row * DIMZ + wg * 32);
#pragma unroll
        for (int q = 0; q < 8; q++)
            op[q] = make_float4(zc[4 * q], zc[4 * q + 1], zc[4 * q + 2], zc[4 * q + 3]);
    }

    __syncthreads();
    if (w == 0) TCGEN05_DEALLOC(tb, TMEM_NCOLS);
#endif  // CNF_HAS_TCGEN05
}

extern "C" void kernel_launch(void* const* d_in, const int* in_sizes, int n_in,
                              void* d_out, int out_size) {
    const float* z0 = (const float*)d_in[0];
    const float* W1 = (const float*)d_in[1];
    const float* b1 = (const float*)d_in[2];
    const float* W2 = (const float*)d_in[3];
    const float* b2 = (const float*)d_in[4];
    const float* W3 = (const float*)d_in[5];
    const float* b3 = (const float*)d_in[6];
    float* out = (float*)d_out;

    cudaFuncSetAttribute(cnf_rk4_kernel, cudaFuncAttributeMaxDynamicSharedMemorySize, SM_TOTAL);
    cnf_rk4_kernel<<<NTILES, NTHREADS, SM_TOTAL>>>(z0, W1, b1, W2, b2, W3, b3, out);
}

// round 4
// speedup vs baseline: 1.0727x; 1.0727x over previous
#include <cuda_runtime.h>
#include <cuda_fp16.h>
#include <cstdint>

#define DIMZ 64
#define HID 256
#define NBATCH 32768
#define NSTEPS 100
#define TILE_M 128
#define NTILES 256
#define NTHREADS 256
#define DT_F 0.01f

// tcgen05 is an sm_103a arch-specific feature: only emit it in the
// arch-specific compilation pass.
#if defined(__CUDA_ARCH__)
#if defined(__CUDA_ARCH_FEAT_SM103_ALL) || \
    (defined(__CUDA_ARCH_SPECIFIC__) && (__CUDA_ARCH_SPECIFIC__ == 1030)) || \
    (defined(__CUDA_ARCH_HAS_FEATURE__) && defined(__CUDA_ARCH_FEAT_SM101_ALL))
#define CNF_HAS_TCGEN05 1
#else
#define CNF_HAS_TCGEN05 0
#endif
#else
#define CNF_HAS_TCGEN05 0
#endif

// ---- TMEM column layout (512 f32 cols, 480 used) ----
#define TM_D12A 0u     // 128 cols: f32 D, hidden GEMMs N-half a (features 0-127)
#define TM_D12B 128u   // 128 cols: f32 D, hidden GEMMs N-half b (features 128-255)
#define TM_AH 256u     // 128 cols: activations f16 packed (K=256), single buffer
#define TM_D3 384u     // 64 cols:  f32 D for GEMM3 (N=64)
#define TM_AZ 448u     // 32 cols:  z input f16 packed (K=64)
#define TMEM_NCOLS 512u

// ---- SMEM byte layout ----
#define SM_TMEMPTR 0
#define SM_MBAR0 8
#define SM_MBAR1 16
#define SM_B1H 32       // 128 x u32 (half2 bias1 pairs)
#define SM_B2H 544      // 128 x u32 (half2 bias2 pairs)
#define SM_B3F 1056     // 64 x f32 bias3
#define SM_W1 2048      // [256 n][64 k] f16, 128B rows, SW128  (32 KB)
#define SM_W2 34816     // [256 n][256 k] f16 blocked atoms     (128 KB)
#define SM_W3 165888    // [64 n][256 k] f16 blocked atoms      (32 KB)
#define SM_TOTAL 198656

// idesc kind::f16: atype=btype=F16(0); dtype F32=(1<<4); N/8<<17; M/16<<24
#define IDESC_F_N128 0x08200010u   // f32 D, N=128, M=128
#define IDESC_F_N64 0x08100010u    // f32 D, N=64,  M=128

// SW128 K-major smem descriptor base: layout=2, version=1, SBO=64, LBO=1
static constexpr uint64_t DESC_BASE_SW128 =
    (uint64_t(2) << 61) | (uint64_t(1) << 46) | (uint64_t(64) << 32) | (uint64_t(1) << 16);

#if CNF_HAS_TCGEN05

__device__ __forceinline__ uint32_t smem_u32(const void* p) {
    uint32_t a;
    asm("{ .reg .u64 t; cvta.to.shared.u64 t, %1; cvt.u32.u64 %0, t; }" : "=r"(a) : "l"(p));
    return a;
}
__device__ __forceinline__ uint32_t elect1() {
    uint32_t r;
    asm volatile("{ .reg .pred p; elect.sync _|p, 0xFFFFFFFF; selp.b32 %0, 1, 0, p; }" : "=r"(r));
    return r;
}
__device__ __forceinline__ uint32_t swz128(uint32_t x) { return x ^ ((x >> 3) & 0x70); }

__device__ __forceinline__ uint32_t pack_f16x2(float lo, float hi) {
    uint32_t d;
    asm("cvt.rn.f16x2.f32 %0, %1, %2;" : "=r"(d) : "f"(hi), "f"(lo));
    return d;
}
__device__ __forceinline__ uint32_t hadd2u(uint32_t a, uint32_t b) {
    uint32_t d;
    asm("add.rn.f16x2 %0, %1, %2;" : "=r"(d) : "r"(a), "r"(b));
    return d;
}
__device__ __forceinline__ uint32_t htanh2(uint32_t a) {
    uint32_t d;
    asm("tanh.approx.f16x2 %0, %1;" : "=r"(d) : "r"(a));
    return d;
}

#define TCGEN05_ALLOC(smem_addr, nCols) \
    asm volatile("tcgen05.alloc.cta_group::1.sync.aligned.shared::cta.b32 [%0], %1;" \
                 :: "r"((uint32_t)(smem_addr)), "r"((uint32_t)(nCols)) : "memory")
#define TCGEN05_DEALLOC(tmem_addr, nCols) \
    asm volatile("tcgen05.dealloc.cta_group::1.sync.aligned.b32 %0, %1;" \
                 :: "r"(tmem_addr), "r"((uint32_t)(nCols)))
#define TCGEN05_WAIT_LD() asm volatile("tcgen05.wait::ld.sync.aligned;" ::: "memory")
#define TCGEN05_WAIT_ST() asm volatile("tcgen05.wait::st.sync.aligned;" ::: "memory")
#define TCGEN05_FENCE_BEFORE() asm volatile("tcgen05.fence::before_thread_sync;" ::: "memory")
#define TCGEN05_FENCE_AFTER() asm volatile("tcgen05.fence::after_thread_sync;" ::: "memory")
#define TCGEN05_COMMIT(mbar) \
    asm volatile("tcgen05.commit.cta_group::1.mbarrier::arrive::one.shared::cluster.b64 [%0];" \
                 :: "r"((uint32_t)(mbar)) : "memory")
#define MBARRIER_INIT(mbar, count) \
    asm volatile("mbarrier.init.shared.b64 [%0], %1;" \
                 :: "r"((uint32_t)(mbar)), "r"((uint32_t)(count)) : "memory")

#define MBARRIER_WAIT_PARITY(mbar_smem_addr, phase_parity) do { \
    uint32_t _mbar = (uint32_t)(mbar_smem_addr); \
    uint32_t _parity = (uint32_t)(phase_parity); \
    uint32_t _done; \
    asm volatile( \
        "{\n\t" \
        ".reg .pred p;\n\t" \
        "mbarrier.try_wait.parity.acquire.cta.shared::cta.b64 p, [%1], %2;\n\t" \
        "selp.b32 %0, 1, 0, p;\n\t" \
        "}" \
        : "=r"(_done) : "r"(_mbar), "r"(_parity) : "memory"); \
    if (!_done) { \
        asm volatile( \
            "{\n\t" \
            ".reg .pred P1;\n\t" \
            "WAIT_LOOP_%=:\n\t" \
            "mbarrier.try_wait.parity.acquire.cta.shared::cta.b64 P1, [%0], %1, 0x989680;\n\t" \
            "@P1 bra.uni WAIT_DONE_%=;\n\t" \
            "bra.uni WAIT_LOOP_%=;\n\t" \
            "WAIT_DONE_%=:\n\t" \
            "}" \
            :: "r"(_mbar), "r"(_parity) : "memory"); \
    } \
} while (0)

#define TCGEN05_LD_32X32B_X32(r, tmem_addr) \
    asm volatile( \
        "tcgen05.ld.sync.aligned.32x32b.x32.b32 " \
        "{%0, %1, %2, %3, %4, %5, %6, %7, " \
        " %8, %9, %10, %11, %12, %13, %14, %15, " \
        " %16, %17, %18, %19, %20, %21, %22, %23, " \
        " %24, %25, %26, %27, %28, %29, %30, %31}, [%32];" \
        : "=r"((r)[0]),  "=r"((r)[1]),  "=r"((r)[2]),  "=r"((r)[3]), \
          "=r"((r)[4]),  "=r"((r)[5]),  "=r"((r)[6]),  "=r"((r)[7]), \
          "=r"((r)[8]),  "=r"((r)[9]),  "=r"((r)[10]), "=r"((r)[11]), \
          "=r"((r)[12]), "=r"((r)[13]), "=r"((r)[14]), "=r"((r)[15]), \
          "=r"((r)[16]), "=r"((r)[17]), "=r"((r)[18]), "=r"((r)[19]), \
          "=r"((r)[20]), "=r"((r)[21]), "=r"((r)[22]), "=r"((r)[23]), \
          "=r"((r)[24]), "=r"((r)[25]), "=r"((r)[26]), "=r"((r)[27]), \
          "=r"((r)[28]), "=r"((r)[29]), "=r"((r)[30]), "=r"((r)[31]) \
        : "r"(tmem_addr))

#define TCGEN05_ST_32X32B_X16(tmem_addr, r) \
    asm volatile( \
        "tcgen05.st.sync.aligned.32x32b.x16.b32 [%0], " \
        "{%1, %2, %3, %4, %5, %6, %7, %8, " \
        " %9, %10, %11, %12, %13, %14, %15, %16};" \
        :: "r"(tmem_addr), \
           "r"((r)[0]),  "r"((r)[1]),  "r"((r)[2]),  "r"((r)[3]), \
           "r"((r)[4]),  "r"((r)[5]),  "r"((r)[6]),  "r"((r)[7]), \
           "r"((r)[8]),  "r"((r)[9]),  "r"((r)[10]), "r"((r)[11]), \
           "r"((r)[12]), "r"((r)[13]), "r"((r)[14]), "r"((r)[15]) \
        : "memory")

__device__ __forceinline__ void mma_f16_ts(uint32_t d, uint32_t a, uint64_t bdesc,
                                           uint32_t idesc, uint32_t accum) {
    asm volatile(
        "{\n\t"
        ".reg .pred p;\n\t"
        "setp.ne.u32 p, %5, 0;\n\t"
        "tcgen05.mma.cta_group::1.kind::f16 [%0], [%1], %2, %3, {%4, %4, %4, %4}, p;\n\t"
        "}"
        :: "r"(d), "r"(a), "l"(bdesc), "r"(idesc), "r"(0u), "r"(accum)
        : "memory");
}

// Half-epilogue (f32 D): read 64 f32 cols of a 128-col N-half (this warp's
// share), pack f16x2, add bias, tanh, store 32 packed cols into AH.
// dbase: D half base col. ahdest: packed destination base col.
// biasPairs: pointer already offset to this half's first bias pair.
__device__ __forceinline__ void half_epi(uint32_t tb, uint32_t dbase, uint32_t ahdest,
                                         const uint32_t* biasPairs, int wg, uint32_t warpoff) {
#pragma unroll
    for (int c = 0; c < 2; c++) {
        const uint32_t cb = (uint32_t)(wg * 64 + c * 32);   // D col offset within half
        uint32_t r[32];
        TCGEN05_LD_32X32B_X32(r, tb + dbase + cb + warpoff);
        TCGEN05_WAIT_LD();
        const uint32_t pb = (uint32_t)(wg * 32 + c * 16);   // packed dest offset
        uint32_t o[16];
#pragma unroll
        for (int j = 0; j < 16; j++) {
            uint32_t p = pack_f16x2(__uint_as_float(r[2 * j]), __uint_as_float(r[2 * j + 1]));
            o[j] = htanh2(hadd2u(p, biasPairs[pb + j]));
        }
        TCGEN05_ST_32X32B_X16(tb + ahdest + pb + warpoff, o);
    }
    TCGEN05_WAIT_ST();
    TCGEN05_FENCE_BEFORE();
}

#endif  // CNF_HAS_TCGEN05

extern "C" __global__ void __launch_bounds__(NTHREADS, 1)
cnf_rk4_kernel(const float* __restrict__ z0,
               const float* __restrict__ W1, const float* __restrict__ b1,
               const float* __restrict__ W2, const float* __restrict__ b2,
               const float* __restrict__ W3, const float* __restrict__ b3,
               float* __restrict__ out) {
#if CNF_HAS_TCGEN05
    extern __shared__ char smem[];
    const uint32_t sb = smem_u32(smem);
    const int tid = threadIdx.x;
    const int w = tid >> 5;
    const int lane = tid & 31;
    const int sp = w & 3;        // TMEM subpartition (SMSP)
    const int wg = w >> 2;       // warpgroup (0/1)
    const uint32_t warpoff = (uint32_t)sp << 21;

    if (w == 0) TCGEN05_ALLOC(sb + SM_TMEMPTR, TMEM_NCOLS);

    // ---- Convert weights to f16 B-operand layouts in SMEM ----
    // W1: global [64 k][256 n] -> B1[n][k], 128B rows, SW128
    for (int i = tid; i < 64 * 256; i += NTHREADS) {
        int k = i >> 8, n = i & 255;
        *(__half*)(smem + SM_W1 + swz128((uint32_t)(n * 128 + k * 2))) = __float2half_rn(W1[i]);
    }
    // W2: global [256 k][256 n] -> blocked atoms: 32 atom-rows x 4 atom-cols
    for (int i = tid; i < 256 * 256; i += NTHREADS) {
        int k = i >> 8, n = i & 255;
        uint32_t off = (uint32_t)((((n >> 3) + (k >> 6) * 32) << 10) + ((n & 7) << 7) + ((k & 63) << 1));
        *(__half*)(smem + SM_W2 + swz128(off)) = __float2half_rn(W2[i]);
    }
    // W3: global [256 k][64 n] -> blocked atoms: 8 atom-rows x 4 atom-cols
    for (int i = tid; i < 256 * 64; i += NTHREADS) {
        int k = i >> 6, n = i & 63;
        uint32_t off = (uint32_t)((((n >> 3) + (k >> 6) * 8) << 10) + ((n & 7) << 7) + ((k & 63) << 1));
        *(__half*)(smem + SM_W3 + swz128(off)) = __float2half_rn(W3[i]);
    }
    // biases as half2 pairs
    for (int i = tid; i < 128; i += NTHREADS) {
        ((uint32_t*)(smem + SM_B1H))[i] = pack_f16x2(b1[2 * i], b1[2 * i + 1]);
        ((uint32_t*)(smem + SM_B2H))[i] = pack_f16x2(b2[2 * i], b2[2 * i + 1]);
    }
    for (int i = tid; i < 64; i += NTHREADS) ((float*)(smem + SM_B3F))[i] = b3[i];

    if (tid == 0) { MBARRIER_INIT(sb + SM_MBAR0, 1); MBARRIER_INIT(sb + SM_MBAR1, 1); }
    __syncthreads();

    uint32_t tb;
    asm volatile("ld.shared.b32 %0, [%1];" : "=r"(tb) : "r"(sb + SM_TMEMPTR));

    const uint32_t* bh1 = (const uint32_t*)(smem + SM_B1H);
    const uint32_t* bh2 = (const uint32_t*)(smem + SM_B2H);

    // ---- Load z tile: thread owns row (sp*32+lane), cols [wg*32, wg*32+32) ----
    const int row = blockIdx.x * TILE_M + sp * 32 + lane;
    float zc[32], acc[32];
    {
        const float4* zp = (const float4*)(z0 + (size_t)row * DIMZ + wg * 32);
#pragma unroll
        for (int q = 0; q < 8; q++) {
            float4 v = zp[q];
            zc[4 * q] = v.x; zc[4 * q + 1] = v.y; zc[4 * q + 2] = v.z; zc[4 * q + 3] = v.w;
        }
#pragma unroll
        for (int j = 0; j < 32; j++) acc[j] = 0.0f;
    }

    // initial A_z = f16(z0)
    {
        uint32_t o[16];
#pragma unroll
        for (int j = 0; j < 16; j++) o[j] = pack_f16x2(zc[2 * j], zc[2 * j + 1]);
        TCGEN05_ST_32X32B_X16(tb + TM_AZ + (uint32_t)(wg * 16) + warpoff, o);
        TCGEN05_WAIT_ST();
        TCGEN05_FENCE_BEFORE();
    }
    __syncthreads();

    const uint64_t dW1 = DESC_BASE_SW128 | (((uint64_t)((sb + SM_W1) >> 4)) & 0x3FFF);
    const uint64_t dW2 = DESC_BASE_SW128 | (((uint64_t)((sb + SM_W2) >> 4)) & 0x3FFF);
    const uint64_t dW3 = DESC_BASE_SW128 | (((uint64_t)((sb + SM_W3) >> 4)) & 0x3FFF);
    // N-half b of W1/W2 starts 128 rows (16 KB = 1024 desc units) later
    const uint64_t dW1b = dW1 + 1024;
    const uint64_t dW2b = dW2 + 1024;

    uint32_t p0 = 0, p1 = 0;

    for (int it = 0; it < NSTEPS * 4; ++it) {
        const int s = it & 3;

        // S1: issue GEMM1 both N-halves (A=AZ, K=64) -> D12A, D12B (f32)
        if (w == 0) {
            TCGEN05_FENCE_AFTER();
            if (elect1()) {
#pragma unroll
                for (int ks = 0; ks < 4; ks++)
                    mma_f16_ts(tb + TM_D12A, tb + TM_AZ + (uint32_t)(ks * 8),
                               dW1 + (uint64_t)(ks * 2), IDESC_F_N128, ks > 0);
                TCGEN05_COMMIT(sb + SM_MBAR0);
#pragma unroll
                for (int ks = 0; ks < 4; ks++)
                    mma_f16_ts(tb + TM_D12B, tb + TM_AZ + (uint32_t)(ks * 8),
                               dW1b + (uint64_t)(ks * 2), IDESC_F_N128, ks > 0);
                TCGEN05_COMMIT(sb + SM_MBAR1);
            }
        }

        // S2: epilogue L1 half a: D12A -> AH[0:64]
        MBARRIER_WAIT_PARITY(sb + SM_MBAR0, p0); p0 ^= 1u;
        TCGEN05_FENCE_AFTER();
        half_epi(tb, TM_D12A, TM_AH, bh1, wg, warpoff);

        // S3: issue GEMM2 half-a K0-7 (reads AH[0:64], writes D12A); no commit.
        // (G2b must NOT start here: its first dispatch would overwrite D12B
        //  before E1b reads it.)
        __syncthreads();
        if (w == 0) {
            TCGEN05_FENCE_AFTER();
            if (elect1()) {
#pragma unroll
                for (int ks = 0; ks < 8; ks++)
                    mma_f16_ts(tb + TM_D12A, tb + TM_AH + (uint32_t)(ks * 8),
                               dW2 + (uint64_t)((ks & 3) * 2 + (ks >> 2) * 2048), IDESC_F_N128, ks > 0);
            }
        }

        // S4: epilogue L1 half b: D12B -> AH[64:128]  (overlaps G2a K0-7)
        MBARRIER_WAIT_PARITY(sb + SM_MBAR1, p1); p1 ^= 1u;
        TCGEN05_FENCE_AFTER();
        half_epi(tb, TM_D12B, TM_AH + 64u, bh1 + 64, wg, warpoff);

        // S5: issue GEMM2 half-a K8-15 (+commit B0) and half-b K0-15 (+commit B1)
        __syncthreads();
        if (w == 0) {
            TCGEN05_FENCE_AFTER();
            if (elect1()) {
#pragma unroll
                for (int ks = 8; ks < 16; ks++)
                    mma_f16_ts(tb + TM_D12A, tb + TM_AH + (uint32_t)(ks * 8),
                               dW2 + (uint64_t)((ks & 3) * 2 + (ks >> 2) * 2048), IDESC_F_N128, 1);
                TCGEN05_COMMIT(sb + SM_MBAR0);
#pragma unroll
                for (int ks = 0; ks < 16; ks++)
                    mma_f16_ts(tb + TM_D12B, tb + TM_AH + (uint32_t)(ks * 8),
                               dW2b + (uint64_t)((ks & 3) * 2 + (ks >> 2) * 2048), IDESC_F_N128, ks > 0);
                TCGEN05_COMMIT(sb + SM_MBAR1);
            }
        }

        // S6: epilogue L2 half a: D12A -> AH[0:64]  (overlaps G2b).
        // Safe: B0 implies G2a done AND (in-order) G2b's reads of AH[0:64]
        // can still be pending? No: G2b also reads AH[0:64] in its K0-7
        // dispatches, which were issued BEFORE commit(B0)? They were issued
        // AFTER commit(B0) in program order but the queue is in-order, so
        // G2b K0-7 may still be running. Its reads cover AH[0:64] — which we
        // are about to overwrite! Therefore wait on B1 is required... BUT
        // in-order execution means we cannot overlap at all that way.
        // Resolution: MMA A-operand reads happen at dispatch consumption;
        // the tensor pipe is in-order, and B1 fires only when G2b is done.
        // To keep the E2a||G2b overlap SOUND, E2a must not touch AH until
        // G2b's AH[0:64] reads are done. G2b K0-7 runs right after G2a
        // K8-15; E2a's first ~512 cycles are LDTM of D12A (no AH writes).
        // That is a heuristic, not a guarantee — so instead we wait B1 here
        // for correctness and accept serialization of E2a after G2b.
        MBARRIER_WAIT_PARITY(sb + SM_MBAR0, p0); p0 ^= 1u;
        MBARRIER_WAIT_PARITY(sb + SM_MBAR1, p1); p1 ^= 1u;
        TCGEN05_FENCE_AFTER();
        half_epi(tb, TM_D12A, TM_AH, bh2, wg, warpoff);

        // S7: issue GEMM3 K0-7 (reads AH[0:64] = L2 half a, writes D3); no commit
        __syncthreads();
        if (w == 0) {
            TCGEN05_FENCE_AFTER();
            if (elect1()) {
#pragma unroll
                for (int ks = 0; ks < 8; ks++)
                    mma_f16_ts(tb + TM_D3, tb + TM_AH + (uint32_t)(ks * 8),
                               dW3 + (uint64_t)((ks & 3) * 2 + (ks >> 2) * 512), IDESC_F_N64, ks > 0);
            }
        }

        // S8: epilogue L2 half b: D12B -> AH[64:128]  (overlaps G3 K0-7)
        half_epi(tb, TM_D12B, TM_AH + 64u, bh2 + 64, wg, warpoff);

        // S9: issue GEMM3 K8-15 + commit B0
        __syncthreads();
        if (w == 0) {
            TCGEN05_FENCE_AFTER();
            if (elect1()) {
#pragma unroll
                for (int ks = 8; ks < 16; ks++)
                    mma_f16_ts(tb + TM_D3, tb + TM_AH + (uint32_t)(ks * 8),
                               dW3 + (uint64_t)((ks & 3) * 2 + (ks >> 2) * 512), IDESC_F_N64, 1);
                TCGEN05_COMMIT(sb + SM_MBAR0);
            }
        }

        // S10: RK4 stage epilogue: read D3 (f32), update state, write A_z
        MBARRIER_WAIT_PARITY(sb + SM_MBAR0, p0); p0 ^= 1u;
        TCGEN05_FENCE_AFTER();
        {
            uint32_t r[32];
            TCGEN05_LD_32X32B_X32(r, tb + TM_D3 + (uint32_t)(wg * 32) + warpoff);
            TCGEN05_WAIT_LD();
            const float* b3s = (const float*)(smem + SM_B3F) + wg * 32;
            float zin[32];
            if (s == 0) {
#pragma unroll
                for (int j = 0; j < 32; j++) {
                    float f = __uint_as_float(r[j]) + b3s[j];
                    acc[j] = f;
                    zin[j] = fmaf(0.5f * DT_F, f, zc[j]);
                }
            } else if (s == 1) {
#pragma unroll
                for (int j = 0; j < 32; j++) {
                    float f = __uint_as_float(r[j]) + b3s[j];
                    acc[j] = fmaf(2.0f, f, acc[j]);
                    zin[j] = fmaf(0.5f * DT_F, f, zc[j]);
                }
            } else if (s == 2) {
#pragma unroll
                for (int j = 0; j < 32; j++) {
                    float f = __uint_as_float(r[j]) + b3s[j];
                    acc[j] = fmaf(2.0f, f, acc[j]);
                    zin[j] = fmaf(DT_F, f, zc[j]);
                }
            } else {
#pragma unroll
                for (int j = 0; j < 32; j++) {
                    float f = __uint_as_float(r[j]) + b3s[j];
                    acc[j] += f;
                    zc[j] = fmaf(DT_F / 6.0f, acc[j], zc[j]);
                    zin[j] = zc[j];
                }
            }
            uint32_t o[16];
#pragma unroll
            for (int j = 0; j < 16; j++) o[j] = pack_f16x2(zin[2 * j], zin[2 * j + 1]);
            TCGEN05_ST_32X32B_X16(tb + TM_AZ + (uint32_t)(wg * 16) + warpoff, o);
            TCGEN05_WAIT_ST();
            TCGEN05_FENCE_BEFORE();
        }
        __syncthreads();  // AZ + AH writes visible -> next S1
    }

    // ---- write result ----
    {
        float4* op = (float4*)(out + (size_t)row * DIMZ + wg * 32);
#pragma unroll
        for (int q = 0; q < 8; q++)
            op[q] = make_float4(zc[4 * q], zc[4 * q + 1], zc[4 * q + 2], zc[4 * q + 3]);
    }

    __syncthreads();
    if (w == 0) TCGEN05_DEALLOC(tb, TMEM_NCOLS);
#endif  // CNF_HAS_TCGEN05
}

extern "C" void kernel_launch(void* const* d_in, const int* in_sizes, int n_in,
                              void* d_out, int out_size) {
    const float* z0 = (const float*)d_in[0];
    const float* W1 = (const float*)d_in[1];
    const float* b1 = (const float*)d_in[2];
    const float* W2 = (const float*)d_in[3];
    const float* b2 = (const float*)d_in[4];
    const float* W3 = (const float*)d_in[5];
    const float* b3 = (const float*)d_in[6];
    float* out = (float*)d_out;

    cudaFuncSetAttribute(cnf_rk4_kernel, cudaFuncAttributeMaxDynamicSharedMemorySize, SM_TOTAL);
    cnf_rk4_kernel<<<NTILES, NTHREADS, SM_TOTAL>>>(z0, W1, b1, W2, b2, W3, b3, out);
}

// round 5
// speedup vs baseline: 1.2001x; 1.1188x over previous
#include <cuda_runtime.h>
#include <cuda_fp16.h>
#include <cstdint>

#define DIMZ 64
#define HID 256
#define NBATCH 32768
#define NSTEPS 100
#define TILE_M 128
#define NTILES 256
#define NTHREADS 288   // 8 worker warps + 1 MMA warp
#define DT_F 0.01f

// tcgen05 is sm_103a arch-specific: only emit in the arch-specific pass.
#if defined(__CUDA_ARCH__)
#if defined(__CUDA_ARCH_FEAT_SM103_ALL) || \
    (defined(__CUDA_ARCH_SPECIFIC__) && (__CUDA_ARCH_SPECIFIC__ == 1030)) || \
    (defined(__CUDA_ARCH_HAS_FEATURE__) && defined(__CUDA_ARCH_FEAT_SM101_ALL))
#define CNF_HAS_TCGEN05 1
#else
#define CNF_HAS_TCGEN05 0
#endif
#else
#define CNF_HAS_TCGEN05 0
#endif

// ---- TMEM columns (480/512 used) ----
// [0,64)    D0  : L2 quarter ping  (also L1-h0 low half)
// [64,128)  D1  : L2 quarter pong  (also L1-h0 high half)
// [128,256) AH1 : layer-1 activations, f16 packed (K=256)
// [256,384) DW1 : L1-h1 D (f32)  --- later reused as AH2 (f16 packed)
// [384,448) D3  : f32 D for GEMM3
// [448,480) AZ  : z input, f16 packed (K=64)
#define TMEM_NCOLS 512u

// ---- SMEM byte layout ----
#define SM_TMEMPTR 0
#define SM_C0 8
#define SM_C1 16
#define SM_CA 24
#define SM_F0 32
#define SM_F1 40
#define SM_H1A 48
#define SM_H1 56
#define SM_H2A 64
#define SM_H2 72
#define SM_Z 80
#define SM_B1H 96       // 128 x u32 (half2 bias1 pairs)
#define SM_B2H 608      // 128 x u32 (half2 bias2 pairs)
#define SM_B3F 1120     // 64 x f32 bias3
#define SM_W1 2048      // [256 n][64 k] f16, 128B rows, SW128  (32 KB)
#define SM_W2 34816     // [256 n][256 k] f16 blocked atoms     (128 KB)
#define SM_W3 165888    // [64 n][256 k] f16 blocked atoms      (32 KB)
#define SM_TOTAL 198656

// idesc kind::f16: atype=btype=F16(0); dtype F32=(1<<4); N/8<<17; M/16<<24
#define IDESC_F_N128 0x08200010u
#define IDESC_F_N64 0x08100010u

static constexpr uint64_t DESC_BASE_SW128 =
    (uint64_t(2) << 61) | (uint64_t(1) << 46) | (uint64_t(64) << 32) | (uint64_t(1) << 16);

#if CNF_HAS_TCGEN05

__device__ __forceinline__ uint32_t smem_u32(const void* p) {
    uint32_t a;
    asm("{ .reg .u64 t; cvta.to.shared.u64 t, %1; cvt.u32.u64 %0, t; }" : "=r"(a) : "l"(p));
    return a;
}
__device__ __forceinline__ uint32_t elect1() {
    uint32_t r;
    asm volatile("{ .reg .pred p; elect.sync _|p, 0xFFFFFFFF; selp.b32 %0, 1, 0, p; }" : "=r"(r));
    return r;
}
__device__ __forceinline__ uint32_t swz128(uint32_t x) { return x ^ ((x >> 3) & 0x70); }

__device__ __forceinline__ uint32_t pack_f16x2(float lo, float hi) {
    uint32_t d;
    asm("cvt.rn.f16x2.f32 %0, %1, %2;" : "=r"(d) : "f"(hi), "f"(lo));
    return d;
}
__device__ __forceinline__ uint32_t hadd2u(uint32_t a, uint32_t b) {
    uint32_t d;
    asm("add.rn.f16x2 %0, %1, %2;" : "=r"(d) : "r"(a), "r"(b));
    return d;
}
__device__ __forceinline__ uint32_t htanh2(uint32_t a) {
    uint32_t d;
    asm("tanh.approx.f16x2 %0, %1;" : "=r"(d) : "r"(a));
    return d;
}

#define TCGEN05_ALLOC(smem_addr, nCols) \
    asm volatile("tcgen05.alloc.cta_group::1.sync.aligned.shared::cta.b32 [%0], %1;" \
                 :: "r"((uint32_t)(smem_addr)), "r"((uint32_t)(nCols)) : "memory")
#define TCGEN05_DEALLOC(tmem_addr, nCols) \
    asm volatile("tcgen05.dealloc.cta_group::1.sync.aligned.b32 %0, %1;" \
                 :: "r"(tmem_addr), "r"((uint32_t)(nCols)))
#define TCGEN05_WAIT_LD() asm volatile("tcgen05.wait::ld.sync.aligned;" ::: "memory")
#define TCGEN05_WAIT_ST() asm volatile("tcgen05.wait::st.sync.aligned;" ::: "memory")
#define TCGEN05_FENCE_BEFORE() asm volatile("tcgen05.fence::before_thread_sync;" ::: "memory")
#define TCGEN05_FENCE_AFTER() asm volatile("tcgen05.fence::after_thread_sync;" ::: "memory")
#define TCGEN05_COMMIT(mbar) \
    asm volatile("tcgen05.commit.cta_group::1.mbarrier::arrive::one.shared::cluster.b64 [%0];" \
                 :: "r"((uint32_t)(mbar)) : "memory")
#define MBARRIER_INIT(mbar, count) \
    asm volatile("mbarrier.init.shared.b64 [%0], %1;" \
                 :: "r"((uint32_t)(mbar)), "r"((uint32_t)(count)) : "memory")
#define MBARRIER_ARRIVE(mbar) \
    asm volatile("mbarrier.arrive.shared.b64 _, [%0];" :: "r"((uint32_t)(mbar)) : "memory")
#define FENCE_PROXY_ASYNC() asm volatile("fence.proxy.async.shared::cta;" ::: "memory")

#define MBARRIER_WAIT_PARITY(mbar_smem_addr, phase_parity) do { \
    uint32_t _mbar = (uint32_t)(mbar_smem_addr); \
    uint32_t _parity = (uint32_t)(phase_parity); \
    uint32_t _done; \
    asm volatile( \
        "{\n\t" \
        ".reg .pred p;\n\t" \
        "mbarrier.try_wait.parity.acquire.cta.shared::cta.b64 p, [%1], %2;\n\t" \
        "selp.b32 %0, 1, 0, p;\n\t" \
        "}" \
        : "=r"(_done) : "r"(_mbar), "r"(_parity) : "memory"); \
    if (!_done) { \
        asm volatile( \
            "{\n\t" \
            ".reg .pred P1;\n\t" \
            "WAIT_LOOP_%=:\n\t" \
            "mbarrier.try_wait.parity.acquire.cta.shared::cta.b64 P1, [%0], %1, 0x989680;\n\t" \
            "@P1 bra.uni WAIT_DONE_%=;\n\t" \
            "bra.uni WAIT_LOOP_%=;\n\t" \
            "WAIT_DONE_%=:\n\t" \
            "}" \
            :: "r"(_mbar), "r"(_parity) : "memory"); \
    } \
} while (0)

#define TCGEN05_LD_32X32B_X32(r, tmem_addr) \
    asm volatile( \
        "tcgen05.ld.sync.aligned.32x32b.x32.b32 " \
        "{%0, %1, %2, %3, %4, %5, %6, %7, " \
        " %8, %9, %10, %11, %12, %13, %14, %15, " \
        " %16, %17, %18, %19, %20, %21, %22, %23, " \
        " %24, %25, %26, %27, %28, %29, %30, %31}, [%32];" \
        : "=r"((r)[0]),  "=r"((r)[1]),  "=r"((r)[2]),  "=r"((r)[3]), \
          "=r"((r)[4]),  "=r"((r)[5]),  "=r"((r)[6]),  "=r"((r)[7]), \
          "=r"((r)[8]),  "=r"((r)[9]),  "=r"((r)[10]), "=r"((r)[11]), \
          "=r"((r)[12]), "=r"((r)[13]), "=r"((r)[14]), "=r"((r)[15]), \
          "=r"((r)[16]), "=r"((r)[17]), "=r"((r)[18]), "=r"((r)[19]), \
          "=r"((r)[20]), "=r"((r)[21]), "=r"((r)[22]), "=r"((r)[23]), \
          "=r"((r)[24]), "=r"((r)[25]), "=r"((r)[26]), "=r"((r)[27]), \
          "=r"((r)[28]), "=r"((r)[29]), "=r"((r)[30]), "=r"((r)[31]) \
        : "r"(tmem_addr))

#define TCGEN05_ST_32X32B_X16(tmem_addr, r) \
    asm volatile( \
        "tcgen05.st.sync.aligned.32x32b.x16.b32 [%0], " \
        "{%1, %2, %3, %4, %5, %6, %7, %8, " \
        " %9, %10, %11, %12, %13, %14, %15, %16};" \
        :: "r"(tmem_addr), \
           "r"((r)[0]),  "r"((r)[1]),  "r"((r)[2]),  "r"((r)[3]), \
           "r"((r)[4]),  "r"((r)[5]),  "r"((r)[6]),  "r"((r)[7]), \
           "r"((r)[8]),  "r"((r)[9]),  "r"((r)[10]), "r"((r)[11]), \
           "r"((r)[12]), "r"((r)[13]), "r"((r)[14]), "r"((r)[15]) \
        : "memory")

__device__ __forceinline__ void mma_f16_ts(uint32_t d, uint32_t a, uint64_t bdesc,
                                           uint32_t idesc, uint32_t accum) {
    asm volatile(
        "{\n\t"
        ".reg .pred p;\n\t"
        "setp.ne.u32 p, %5, 0;\n\t"
        "tcgen05.mma.cta_group::1.kind::f16 [%0], [%1], %2, %3, {%4, %4, %4, %4}, p;\n\t"
        "}"
        :: "r"(d), "r"(a), "l"(bdesc), "r"(idesc), "r"(0u), "r"(accum)
        : "memory");
}

// Epilogue sub-chunk: LDTM 32 f32 D cols at dsrc, +bias, tanh, store 16 packed
// f16x2 cols at adst. Ends with WAIT_ST (stores drained, not yet fenced).
__device__ __forceinline__ void epi32(uint32_t tb, uint32_t dsrc, uint32_t adst,
                                      const uint32_t* bias16, uint32_t warpoff) {
    uint32_t r[32];
    TCGEN05_LD_32X32B_X32(r, tb + dsrc + warpoff);
    TCGEN05_WAIT_LD();
    uint32_t o[16];
#pragma unroll
    for (int j = 0; j < 16; j++) {
        uint32_t p = pack_f16x2(__uint_as_float(r[2 * j]), __uint_as_float(r[2 * j + 1]));
        o[j] = htanh2(hadd2u(p, bias16[j]));
    }
    TCGEN05_ST_32X32B_X16(tb + adst + warpoff, o);
    TCGEN05_WAIT_ST();
}

#endif  // CNF_HAS_TCGEN05

extern "C" __global__ void __launch_bounds__(NTHREADS, 1)
cnf_rk4_kernel(const float* __restrict__ z0,
               const float* __restrict__ W1, const float* __restrict__ b1,
               const float* __restrict__ W2, const float* __restrict__ b2,
               const float* __restrict__ W3, const float* __restrict__ b3,
               float* __restrict__ out) {
#if CNF_HAS_TCGEN05
    extern __shared__ char smem[];
    const uint32_t sb = smem_u32(smem);
    const int tid = threadIdx.x;
    const int w = tid >> 5;
    const int lane = tid & 31;

    if (w == 8) TCGEN05_ALLOC(sb + SM_TMEMPTR, TMEM_NCOLS);

    // ---- Weights -> f16 B-operand layouts in SMEM (all 9 warps help) ----
    for (int i = tid; i < 64 * 256; i += NTHREADS) {
        int k = i >> 8, n = i & 255;
        *(__half*)(smem + SM_W1 + swz128((uint32_t)(n * 128 + k * 2))) = __float2half_rn(W1[i]);
    }
    for (int i = tid; i < 256 * 256; i += NTHREADS) {
        int k = i >> 8, n = i & 255;
        uint32_t off = (uint32_t)((((n >> 3) + (k >> 6) * 32) << 10) + ((n & 7) << 7) + ((k & 63) << 1));
        *(__half*)(smem + SM_W2 + swz128(off)) = __float2half_rn(W2[i]);
    }
    for (int i = tid; i < 256 * 64; i += NTHREADS) {
        int k = i >> 6, n = i & 63;
        uint32_t off = (uint32_t)((((n >> 3) + (k >> 6) * 8) << 10) + ((n & 7) << 7) + ((k & 63) << 1));
        *(__half*)(smem + SM_W3 + swz128(off)) = __float2half_rn(W3[i]);
    }
    for (int i = tid; i < 128; i += NTHREADS) {
        ((uint32_t*)(smem + SM_B1H))[i] = pack_f16x2(b1[2 * i], b1[2 * i + 1]);
        ((uint32_t*)(smem + SM_B2H))[i] = pack_f16x2(b2[2 * i], b2[2 * i + 1]);
    }
    for (int i = tid; i < 64; i += NTHREADS) ((float*)(smem + SM_B3F))[i] = b3[i];

    if (tid == 0) {
        MBARRIER_INIT(sb + SM_C0, 1);  MBARRIER_INIT(sb + SM_C1, 1);
        MBARRIER_INIT(sb + SM_CA, 1);
        MBARRIER_INIT(sb + SM_F0, 8);  MBARRIER_INIT(sb + SM_F1, 8);
        MBARRIER_INIT(sb + SM_H1A, 8); MBARRIER_INIT(sb + SM_H1, 8);
        MBARRIER_INIT(sb + SM_H2A, 8); MBARRIER_INIT(sb + SM_H2, 8);
        MBARRIER_INIT(sb + SM_Z, 8);
    }
    FENCE_PROXY_ASYNC();     // order generic-proxy weight/mbar stores vs async proxy
    __syncthreads();

    uint32_t tb;
    asm volatile("ld.shared.b32 %0, [%1];" : "=r"(tb) : "r"(sb + SM_TMEMPTR));

    if (w == 8) {
        // ================= MMA-issue warp =================
        const uint64_t dW1 = DESC_BASE_SW128 | (((uint64_t)((sb + SM_W1) >> 4)) & 0x3FFF);
        const uint64_t dW2 = DESC_BASE_SW128 | (((uint64_t)((sb + SM_W2) >> 4)) & 0x3FFF);
        const uint64_t dW3 = DESC_BASE_SW128 | (((uint64_t)((sb + SM_W3) >> 4)) & 0x3FFF);
        const uint64_t dW1b = dW1 + 1024;   // W1 n-half b (+16KB)

        uint32_t pz = 0, ph1a = 0, ph1 = 0, ph2a = 0, ph2 = 0, pf0 = 0, pf1 = 0;

        for (int it = 0; it < NSTEPS * 4; ++it) {
            // AZ ready
            MBARRIER_WAIT_PARITY(sb + SM_Z, pz); pz ^= 1u;
            TCGEN05_FENCE_AFTER();
            if (elect1()) {
                // G1-h0 -> cols[0,128); G1-h1 -> cols[256,384)
#pragma unroll
                for (int ks = 0; ks < 4; ks++)
                    mma_f16_ts(tb + 0u, tb + 448u + (uint32_t)(ks * 8),
                               dW1 + (uint64_t)(ks * 2), IDESC_F_N128, ks > 0);
                TCGEN05_COMMIT(sb + SM_C0);
#pragma unroll
                for (int ks = 0; ks < 4; ks++)
                    mma_f16_ts(tb + 256u, tb + 448u + (uint32_t)(ks * 8),
                               dW1b + (uint64_t)(ks * 2), IDESC_F_N128, ks > 0);
                TCGEN05_COMMIT(sb + SM_C1);
            }
            // AH1 low half stored -> start G2 Q0/Q1 K0-7
            MBARRIER_WAIT_PARITY(sb + SM_H1A, ph1a); ph1a ^= 1u;
            TCGEN05_FENCE_AFTER();
            if (elect1()) {
#pragma unroll
                for (int ks = 0; ks < 8; ks++)
                    mma_f16_ts(tb + 0u, tb + 128u + (uint32_t)(ks * 8),
                               dW2 + (uint64_t)((ks & 3) * 2 + (ks >> 2) * 2048), IDESC_F_N64, ks > 0);
#pragma unroll
                for (int ks = 0; ks < 8; ks++)
                    mma_f16_ts(tb + 64u, tb + 128u + (uint32_t)(ks * 8),
                               dW2 + (uint64_t)(512 + (ks & 3) * 2 + (ks >> 2) * 2048), IDESC_F_N64, ks > 0);
            }
            // AH1 full -> finish Q0/Q1
            MBARRIER_WAIT_PARITY(sb + SM_H1, ph1); ph1 ^= 1u;
            TCGEN05_FENCE_AFTER();
            if (elect1()) {
#pragma unroll
                for (int ks = 8; ks < 16; ks++)
                    mma_f16_ts(tb + 0u, tb + 128u + (uint32_t)(ks * 8),
                               dW2 + (uint64_t)((ks & 3) * 2 + (ks >> 2) * 2048), IDESC_F_N64, 1);
                TCGEN05_COMMIT(sb + SM_C0);
#pragma unroll
                for (int ks = 8; ks < 16; ks++)
                    mma_f16_ts(tb + 64u, tb + 128u + (uint32_t)(ks * 8),
                               dW2 + (uint64_t)(512 + (ks & 3) * 2 + (ks >> 2) * 2048), IDESC_F_N64, 1);
                TCGEN05_COMMIT(sb + SM_C1);
            }
            // D0 free (E2-Q0 done) -> Q2
            MBARRIER_WAIT_PARITY(sb + SM_F0, pf0); pf0 ^= 1u;
            TCGEN05_FENCE_AFTER();
            if (elect1()) {
#pragma unroll
                for (int ks = 0; ks < 16; ks++)
                    mma_f16_ts(tb + 0u, tb + 128u + (uint32_t)(ks * 8),
                               dW2 + (uint64_t)(1024 + (ks & 3) * 2 + (ks >> 2) * 2048), IDESC_F_N64, ks > 0);
                TCGEN05_COMMIT(sb + SM_C0);
            }
            // D1 free (E2-Q1 done) -> Q3
            MBARRIER_WAIT_PARITY(sb + SM_F1, pf1); pf1 ^= 1u;
            TCGEN05_FENCE_AFTER();
            if (elect1()) {
#pragma unroll
                for (int ks = 0; ks < 16; ks++)
                    mma_f16_ts(tb + 64u, tb + 128u + (uint32_t)(ks * 8),
                               dW2 + (uint64_t)(1536 + (ks & 3) * 2 + (ks >> 2) * 2048), IDESC_F_N64, ks > 0);
                TCGEN05_COMMIT(sb + SM_C1);
            }
            // AH2 low half stored -> G3 K0-7
            MBARRIER_WAIT_PARITY(sb + SM_H2A, ph2a); ph2a ^= 1u;
            TCGEN05_FENCE_AFTER();
            if (elect1()) {
#pragma unroll
                for (int ks = 0; ks < 8; ks++)
                    mma_f16_ts(tb + 384u, tb + 256u + (uint32_t)(ks * 8),
                               dW3 + (uint64_t)((ks & 3) * 2 + (ks >> 2) * 512), IDESC_F_N64, ks > 0);
            }
            // AH2 full -> finish G3
            MBARRIER_WAIT_PARITY(sb + SM_H2, ph2); ph2 ^= 1u;
            TCGEN05_FENCE_AFTER();
            if (elect1()) {
#pragma unroll
                for (int ks = 8; ks < 16; ks++)
                    mma_f16_ts(tb + 384u, tb + 256u + (uint32_t)(ks * 8),
                               dW3 + (uint64_t)((ks & 3) * 2 + (ks >> 2) * 512), IDESC_F_N64, 1);
                TCGEN05_COMMIT(sb + SM_CA);
            }
        }
    } else {
        // ================= worker warps (0-7) =================
        const int sp = w & 3;
        const int wg = w >> 2;
        const uint32_t warpoff = (uint32_t)sp << 21;
        const uint32_t wg32 = (uint32_t)(wg * 32);
        const uint32_t wg16 = (uint32_t)(wg * 16);
        const uint32_t wg64 = (uint32_t)(wg * 64);

        const uint32_t* bh1 = (const uint32_t*)(smem + SM_B1H);
        const uint32_t* bh2 = (const uint32_t*)(smem + SM_B2H);
        const float* b3s = (const float*)(smem + SM_B3F) + wg * 32;

        const int row = blockIdx.x * TILE_M + sp * 32 + lane;
        float zc[32], acc[32];
        {
            const float4* zp = (const float4*)(z0 + (size_t)row * DIMZ + wg * 32);
#pragma unroll
            for (int q = 0; q < 8; q++) {
                float4 v = zp[q];
                zc[4 * q] = v.x; zc[4 * q + 1] = v.y; zc[4 * q + 2] = v.z; zc[4 * q + 3] = v.w;
            }
#pragma unroll
            for (int j = 0; j < 32; j++) acc[j] = 0.0f;
        }
        // initial AZ
        {
            uint32_t o[16];
#pragma unroll
            for (int j = 0; j < 16; j++) o[j] = pack_f16x2(zc[2 * j], zc[2 * j + 1]);
            TCGEN05_ST_32X32B_X16(tb + 448u + wg16 + warpoff, o);
            TCGEN05_WAIT_ST();
            TCGEN05_FENCE_BEFORE();
            if (elect1()) MBARRIER_ARRIVE(sb + SM_Z);
        }

        uint32_t pc0 = 0, pc1 = 0, pca = 0;

        for (int it = 0; it < NSTEPS * 4; ++it) {
            const int s = it & 3;

            // ---- E1 h0: D cols[0,128) -> AH1[0:64 packed] ----
            MBARRIER_WAIT_PARITY(sb + SM_C0, pc0); pc0 ^= 1u;
            TCGEN05_FENCE_AFTER();
            epi32(tb, wg64,       128u + wg32,       bh1 + wg32, warpoff);
            epi32(tb, wg64 + 32u, 128u + wg32 + 16u, bh1 + wg32 + 16, warpoff);
            TCGEN05_FENCE_BEFORE();
            if (elect1()) MBARRIER_ARRIVE(sb + SM_H1A);

            // ---- E1 h1: D cols[256,384) -> AH1[64:128 packed] ----
            MBARRIER_WAIT_PARITY(sb + SM_C1, pc1); pc1 ^= 1u;
            TCGEN05_FENCE_AFTER();
            epi32(tb, 256u + wg64,       128u + 64u + wg32,       bh1 + 64 + wg32, warpoff);
            epi32(tb, 256u + wg64 + 32u, 128u + 64u + wg32 + 16u, bh1 + 64 + wg32 + 16, warpoff);
            TCGEN05_FENCE_BEFORE();
            if (elect1()) MBARRIER_ARRIVE(sb + SM_H1);

            // ---- E2 Q0 (D0) -> AH2[0:32 packed] ----
            MBARRIER_WAIT_PARITY(sb + SM_C0, pc0); pc0 ^= 1u;
            TCGEN05_FENCE_AFTER();
            epi32(tb, wg32, 256u + wg16, bh2 + wg16, warpoff);
            TCGEN05_FENCE_BEFORE();
            if (elect1()) MBARRIER_ARRIVE(sb + SM_F0);

            // ---- E2 Q1 (D1) -> AH2[32:64 packed] ----
            MBARRIER_WAIT_PARITY(sb + SM_C1, pc1); pc1 ^= 1u;
            TCGEN05_FENCE_AFTER();
            epi32(tb, 64u + wg32, 256u + 32u + wg16, bh2 + 32 + wg16, warpoff);
            TCGEN05_FENCE_BEFORE();
            if (elect1()) { MBARRIER_ARRIVE(sb + SM_F1); MBARRIER_ARRIVE(sb + SM_H2A); }

            // ---- E2 Q2 (D0) -> AH2[64:96 packed] ----
            MBARRIER_WAIT_PARITY(sb + SM_C0, pc0); pc0 ^= 1u;
            TCGEN05_FENCE_AFTER();
            epi32(tb, wg32, 256u + 64u + wg16, bh2 + 64 + wg16, warpoff);
            TCGEN05_FENCE_BEFORE();

            // ---- E2 Q3 (D1) -> AH2[96:128 packed] ----
            MBARRIER_WAIT_PARITY(sb + SM_C1, pc1); pc1 ^= 1u;
            TCGEN05_FENCE_AFTER();
            epi32(tb, 64u + wg32, 256u + 96u + wg16, bh2 + 96 + wg16, warpoff);
            TCGEN05_FENCE_BEFORE();
            if (elect1()) MBARRIER_ARRIVE(sb + SM_H2);

            // ---- E3 + RK4 stage update ----
            MBARRIER_WAIT_PARITY(sb + SM_CA, pca); pca ^= 1u;
            TCGEN05_FENCE_AFTER();
            {
                uint32_t r[32];
                TCGEN05_LD_32X32B_X32(r, tb + 384u + wg32 + warpoff);
                TCGEN05_WAIT_LD();
                float zin[32];
                if (s == 0) {
#pragma unroll
                    for (int j = 0; j < 32; j++) {
                        float f = __uint_as_float(r[j]) + b3s[j];
                        acc[j] = f;
                        zin[j] = fmaf(0.5f * DT_F, f, zc[j]);
                    }
                } else if (s == 1) {
#pragma unroll
                    for (int j = 0; j < 32; j++) {
                        float f = __uint_as_float(r[j]) + b3s[j];
                        acc[j] = fmaf(2.0f, f, acc[j]);
                        zin[j] = fmaf(0.5f * DT_F, f, zc[j]);
                    }
                } else if (s == 2) {
#pragma unroll
                    for (int j = 0; j < 32; j++) {
                        float f = __uint_as_float(r[j]) + b3s[j];
                        acc[j] = fmaf(2.0f, f, acc[j]);
                        zin[j] = fmaf(DT_F, f, zc[j]);
                    }
                } else {
#pragma unroll
                    for (int j = 0; j < 32; j++) {
                        float f = __uint_as_float(r[j]) + b3s[j];
                        acc[j] += f;
                        zc[j] = fmaf(DT_F / 6.0f, acc[j], zc[j]);
                        zin[j] = zc[j];
                    }
                }
                uint32_t o[16];
#pragma unroll
                for (int j = 0; j < 16; j++) o[j] = pack_f16x2(zin[2 * j], zin[2 * j + 1]);
                TCGEN05_ST_32X32B_X16(tb + 448u + wg16 + warpoff, o);
                TCGEN05_WAIT_ST();
                TCGEN05_FENCE_BEFORE();
                if (elect1()) MBARRIER_ARRIVE(sb + SM_Z);
            }
        }

        // ---- write result ----
        {
            float4* op = (float4*)(out + (size_t)row * DIMZ + wg * 32);
#pragma unroll
            for (int q = 0; q < 8; q++)
                op[q] = make_float4(zc[4 * q], zc[4 * q + 1], zc[4 * q + 2], zc[4 * q + 3]);
        }
    }

    __syncthreads();
    if (w == 8) TCGEN05_DEALLOC(tb, TMEM_NCOLS);
#endif  // CNF_HAS_TCGEN05
}

extern "C" void kernel_launch(void* const* d_in, const int* in_sizes, int n_in,
                              void* d_out, int out_size) {
    const float* z0 = (const float*)d_in[0];
    const float* W1 = (const float*)d_in[1];
    const float* b1 = (const float*)d_in[2];
    const float* W2 = (const float*)d_in[3];
    const float* b2 = (const float*)d_in[4];
    const float* W3 = (const float*)d_in[5];
    const float* b3 = (const float*)d_in[6];
    float* out = (float*)d_out;

    cudaFuncSetAttribute(cnf_rk4_kernel, cudaFuncAttributeMaxDynamicSharedMemorySize, SM_TOTAL);
    cnf_rk4_kernel<<<NTILES, NTHREADS, SM_TOTAL>>>(z0, W1, b1, W2, b2, W3, b3, out);
}

// round 8
// speedup vs baseline: 1.2519x; 1.0431x over previous
#include <cuda_runtime.h>
#include <cuda_fp16.h>
#include <cstdint>

#define DIMZ 64
#define HID 256
#define NBATCH 32768
#define NSTEPS 100
#define TILE_M 128
#define NTILES 256
#define NTHREADS 288   // 8 worker warps + 1 MMA warp
#define DT_F 0.01f

// tcgen05 is sm_103a arch-specific: only emit in the arch-specific pass.
#if defined(__CUDA_ARCH__)
#if defined(__CUDA_ARCH_FEAT_SM103_ALL) || \
    (defined(__CUDA_ARCH_SPECIFIC__) && (__CUDA_ARCH_SPECIFIC__ == 1030)) || \
    (defined(__CUDA_ARCH_HAS_FEATURE__) && defined(__CUDA_ARCH_FEAT_SM101_ALL))
#define CNF_HAS_TCGEN05 1
#else
#define CNF_HAS_TCGEN05 0
#endif
#else
#define CNF_HAS_TCGEN05 0
#endif

// ---- TMEM columns (480/512) ----
// [0,64)    D0   : G2 Q0, Q3 ping   (also G1h0 D low half)
// [64,128)  D1   : G2 Q1            (also G1h0 D high half)
// [128,256) AH1  : layer-1 activations f16 packed (K=256)
// [256,384) DW1  : G1h1 D (f32) --- then overwritten as AH2 (f16 packed)
// [384,448) D2   : G2 Q2 --- then reused as D3 (f32 D of GEMM3)
// [448,480) AZ   : z input f16 packed (K=64)
#define TMEM_NCOLS 512u

// ---- named HW barriers (bar0 = __syncthreads) ----
#define BAR_Z0 1    // 160: wg0 workers (128) + MMA warp (32)
#define BAR_Z 2     // 288
#define BAR_H1A 3   // 288
#define BAR_H1 4    // 288
#define BAR_H2B 5   // 288
#define BAR_H2 6    // 288
#define BAR_F0 7    // 288

// ---- SMEM byte layout ----
#define SM_TMEMPTR 0
#define SM_C0 8
#define SM_C1 16
#define SM_C2 24
#define SM_C3 32
#define SM_CA 40
#define SM_B1H 96       // 128 x u32 (half2 bias1 pairs)
#define SM_B2H 608      // 128 x u32 (half2 bias2 pairs)
#define SM_B3F 1120     // 64 x f32 bias3
#define SM_W1 2048      // [256 n][64 k] f16, 128B rows, SW128  (32 KB)
#define SM_W2 34816     // [256 n][256 k] f16 blocked atoms     (128 KB)
#define SM_W3 165888    // [64 n][256 k] f16 blocked atoms      (32 KB)
#define SM_TOTAL 198656

// idesc kind::f16: atype=btype=F16(0); dtype F32=(1<<4); N/8<<17; M/16<<24
#define IDESC_F_N128 0x08200010u
#define IDESC_F_N64 0x08100010u

static constexpr uint64_t DESC_BASE_SW128 =
    (uint64_t(2) << 61) | (uint64_t(1) << 46) | (uint64_t(64) << 32) | (uint64_t(1) << 16);

#if CNF_HAS_TCGEN05

__device__ __forceinline__ uint32_t smem_u32(const void* p) {
    uint32_t a;
    asm("{ .reg .u64 t; cvta.to.shared.u64 t, %1; cvt.u32.u64 %0, t; }" : "=r"(a) : "l"(p));
    return a;
}
__device__ __forceinline__ uint32_t elect1() {
    uint32_t r;
    asm volatile("{ .reg .pred p; elect.sync _|p, 0xFFFFFFFF; selp.b32 %0, 1, 0, p; }" : "=r"(r));
    return r;
}
__device__ __forceinline__ uint32_t swz128(uint32_t x) { return x ^ ((x >> 3) & 0x70); }

__device__ __forceinline__ uint32_t pack_f16x2(float lo, float hi) {
    uint32_t d;
    asm("cvt.rn.f16x2.f32 %0, %1, %2;" : "=r"(d) : "f"(hi), "f"(lo));
    return d;
}
__device__ __forceinline__ uint32_t hadd2u(uint32_t a, uint32_t b) {
    uint32_t d;
    asm("add.rn.f16x2 %0, %1, %2;" : "=r"(d) : "r"(a), "r"(b));
    return d;
}
__device__ __forceinline__ uint32_t htanh2(uint32_t a) {
    uint32_t d;
    asm("tanh.approx.f16x2 %0, %1;" : "=r"(d) : "r"(a));
    return d;
}

#define TCGEN05_ALLOC(smem_addr, nCols) \
    asm volatile("tcgen05.alloc.cta_group::1.sync.aligned.shared::cta.b32 [%0], %1;" \
                 :: "r"((uint32_t)(smem_addr)), "r"((uint32_t)(nCols)) : "memory")
#define TCGEN05_DEALLOC(tmem_addr, nCols) \
    asm volatile("tcgen05.dealloc.cta_group::1.sync.aligned.b32 %0, %1;" \
                 :: "r"(tmem_addr), "r"((uint32_t)(nCols)))
#define TCGEN05_WAIT_LD() asm volatile("tcgen05.wait::ld.sync.aligned;" ::: "memory")
#define TCGEN05_WAIT_ST() asm volatile("tcgen05.wait::st.sync.aligned;" ::: "memory")
#define TCGEN05_FENCE_BEFORE() asm volatile("tcgen05.fence::before_thread_sync;" ::: "memory")
#define TCGEN05_FENCE_AFTER() asm volatile("tcgen05.fence::after_thread_sync;" ::: "memory")
#define TCGEN05_COMMIT(mbar) \
    asm volatile("tcgen05.commit.cta_group::1.mbarrier::arrive::one.shared::cluster.b64 [%0];" \
                 :: "r"((uint32_t)(mbar)) : "memory")
#define MBARRIER_INIT(mbar, count) \
    asm volatile("mbarrier.init.shared.b64 [%0], %1;" \
                 :: "r"((uint32_t)(mbar)), "r"((uint32_t)(count)) : "memory")
#define FENCE_PROXY_ASYNC() asm volatile("fence.proxy.async.shared::cta;" ::: "memory")
#define BAR_ARRIVE(id, cnt) \
    asm volatile("bar.arrive %0, %1;" :: "r"((uint32_t)(id)), "r"((uint32_t)(cnt)) : "memory")
#define BAR_SYNC_N(id, cnt) \
    asm volatile("bar.sync %0, %1;" :: "r"((uint32_t)(id)), "r"((uint32_t)(cnt)) : "memory")

#define MBARRIER_WAIT_PARITY(mbar_smem_addr, phase_parity) do { \
    uint32_t _mbar = (uint32_t)(mbar_smem_addr); \
    uint32_t _parity = (uint32_t)(phase_parity); \
    uint32_t _done; \
    asm volatile( \
        "{\n\t" \
        ".reg .pred p;\n\t" \
        "mbarrier.try_wait.parity.acquire.cta.shared::cta.b64 p, [%1], %2;\n\t" \
        "selp.b32 %0, 1, 0, p;\n\t" \
        "}" \
        : "=r"(_done) : "r"(_mbar), "r"(_parity) : "memory"); \
    if (!_done) { \
        asm volatile( \
            "{\n\t" \
            ".reg .pred P1;\n\t" \
            "WAIT_LOOP_%=:\n\t" \
            "mbarrier.try_wait.parity.acquire.cta.shared::cta.b64 P1, [%0], %1, 0x989680;\n\t" \
            "@P1 bra.uni WAIT_DONE_%=;\n\t" \
            "bra.uni WAIT_LOOP_%=;\n\t" \
            "WAIT_DONE_%=:\n\t" \
            "}" \
            :: "r"(_mbar), "r"(_parity) : "memory"); \
    } \
} while (0)

#define TCGEN05_LD_32X32B_X32(r, tmem_addr) \
    asm volatile( \
        "tcgen05.ld.sync.aligned.32x32b.x32.b32 " \
        "{%0, %1, %2, %3, %4, %5, %6, %7, " \
        " %8, %9, %10, %11, %12, %13, %14, %15, " \
        " %16, %17, %18, %19, %20, %21, %22, %23, " \
        " %24, %25, %26, %27, %28, %29, %30, %31}, [%32];" \
        : "=r"((r)[0]),  "=r"((r)[1]),  "=r"((r)[2]),  "=r"((r)[3]), \
          "=r"((r)[4]),  "=r"((r)[5]),  "=r"((r)[6]),  "=r"((r)[7]), \
          "=r"((r)[8]),  "=r"((r)[9]),  "=r"((r)[10]), "=r"((r)[11]), \
          "=r"((r)[12]), "=r"((r)[13]), "=r"((r)[14]), "=r"((r)[15]), \
          "=r"((r)[16]), "=r"((r)[17]), "=r"((r)[18]), "=r"((r)[19]), \
          "=r"((r)[20]), "=r"((r)[21]), "=r"((r)[22]), "=r"((r)[23]), \
          "=r"((r)[24]), "=r"((r)[25]), "=r"((r)[26]), "=r"((r)[27]), \
          "=r"((r)[28]), "=r"((r)[29]), "=r"((r)[30]), "=r"((r)[31]) \
        : "r"(tmem_addr))

#define TCGEN05_ST_32X32B_X16(tmem_addr, r) \
    asm volatile( \
        "tcgen05.st.sync.aligned.32x32b.x16.b32 [%0], " \
        "{%1, %2, %3, %4, %5, %6, %7, %8, " \
        " %9, %10, %11, %12, %13, %14, %15, %16};" \
        :: "r"(tmem_addr), \
           "r"((r)[0]),  "r"((r)[1]),  "r"((r)[2]),  "r"((r)[3]), \
           "r"((r)[4]),  "r"((r)[5]),  "r"((r)[6]),  "r"((r)[7]), \
           "r"((r)[8]),  "r"((r)[9]),  "r"((r)[10]), "r"((r)[11]), \
           "r"((r)[12]), "r"((r)[13]), "r"((r)[14]), "r"((r)[15]) \
        : "memory")

__device__ __forceinline__ void mma_f16_ts(uint32_t d, uint32_t a, uint64_t bdesc,
                                           uint32_t idesc, uint32_t accum) {
    asm volatile(
        "{\n\t"
        ".reg .pred p;\n\t"
        "setp.ne.u32 p, %5, 0;\n\t"
        "tcgen05.mma.cta_group::1.kind::f16 [%0], [%1], %2, %3, {%4, %4, %4, %4}, p;\n\t"
        "}"
        :: "r"(d), "r"(a), "l"(bdesc), "r"(idesc), "r"(0u), "r"(accum)
        : "memory");
}

// Epilogue sub-chunk: LDTM 32 f32 D cols at dsrc (this warp's subpartition),
// pack f16x2, +bias, tanh, store 16 packed cols at adst. Ends drained.
__device__ __forceinline__ void epi32(uint32_t tb, uint32_t dsrc, uint32_t adst,
                                      const uint32_t* bias16, uint32_t warpoff) {
    uint32_t r[32];
    TCGEN05_LD_32X32B_X32(r, tb + dsrc + warpoff);
    TCGEN05_WAIT_LD();
    uint32_t o[16];
#pragma unroll
    for (int j = 0; j < 16; j++) {
        uint32_t p = pack_f16x2(__uint_as_float(r[2 * j]), __uint_as_float(r[2 * j + 1]));
        o[j] = htanh2(hadd2u(p, bias16[j]));
    }
    TCGEN05_ST_32X32B_X16(tb + adst + warpoff, o);
    TCGEN05_WAIT_ST();
}

#endif  // CNF_HAS_TCGEN05

extern "C" __global__ void __launch_bounds__(NTHREADS, 1)
cnf_rk4_kernel(const float* __restrict__ z0,
               const float* __restrict__ W1, const float* __restrict__ b1,
               const float* __restrict__ W2, const float* __restrict__ b2,
               const float* __restrict__ W3, const float* __restrict__ b3,
               float* __restrict__ out) {
#if CNF_HAS_TCGEN05
    extern __shared__ char smem[];
    const uint32_t sb = smem_u32(smem);
    const int tid = threadIdx.x;
    const int w = tid >> 5;
    const int lane = tid & 31;

    if (w == 8) TCGEN05_ALLOC(sb + SM_TMEMPTR, TMEM_NCOLS);

    // ---- Weights -> f16 B-operand layouts in SMEM ----
    for (int i = tid; i < 64 * 256; i += NTHREADS) {
        int k = i >> 8, n = i & 255;
        *(__half*)(smem + SM_W1 + swz128((uint32_t)(n * 128 + k * 2))) = __float2half_rn(W1[i]);
    }
    for (int i = tid; i < 256 * 256; i += NTHREADS) {
        int k = i >> 8, n = i & 255;
        uint32_t off = (uint32_t)((((n >> 3) + (k >> 6) * 32) << 10) + ((n & 7) << 7) + ((k & 63) << 1));
        *(__half*)(smem + SM_W2 + swz128(off)) = __float2half_rn(W2[i]);
    }
    for (int i = tid; i < 256 * 64; i += NTHREADS) {
        int k = i >> 6, n = i & 63;
        uint32_t off = (uint32_t)((((n >> 3) + (k >> 6) * 8) << 10) + ((n & 7) << 7) + ((k & 63) << 1));
        *(__half*)(smem + SM_W3 + swz128(off)) = __float2half_rn(W3[i]);
    }
    for (int i = tid; i < 128; i += NTHREADS) {
        ((uint32_t*)(smem + SM_B1H))[i] = pack_f16x2(b1[2 * i], b1[2 * i + 1]);
        ((uint32_t*)(smem + SM_B2H))[i] = pack_f16x2(b2[2 * i], b2[2 * i + 1]);
    }
    for (int i = tid; i < 64; i += NTHREADS) ((float*)(smem + SM_B3F))[i] = b3[i];

    if (tid == 0) {
        MBARRIER_INIT(sb + SM_C0, 1); MBARRIER_INIT(sb + SM_C1, 1);
        MBARRIER_INIT(sb + SM_C2, 1); MBARRIER_INIT(sb + SM_C3, 1);
        MBARRIER_INIT(sb + SM_CA, 1);
    }
    FENCE_PROXY_ASYNC();
    __syncthreads();

    uint32_t tb;
    asm volatile("ld.shared.b32 %0, [%1];" : "=r"(tb) : "r"(sb + SM_TMEMPTR));

    if (w == 8) {
        // ================= MMA-issue warp =================
        const uint64_t dW1 = DESC_BASE_SW128 | (((uint64_t)((sb + SM_W1) >> 4)) & 0x3FFF);
        const uint64_t dW2 = DESC_BASE_SW128 | (((uint64_t)((sb + SM_W2) >> 4)) & 0x3FFF);
        const uint64_t dW3 = DESC_BASE_SW128 | (((uint64_t)((sb + SM_W3) >> 4)) & 0x3FFF);
        const uint64_t dW1b = dW1 + 1024;

        for (int it = 0; it < NSTEPS * 4; ++it) {
            // Z0: wg0's AZ half ready -> G1 K0-1 of both halves (reads AZ[448,464))
            BAR_SYNC_N(BAR_Z0, 160);
            TCGEN05_FENCE_AFTER();
            if (elect1()) {
                mma_f16_ts(tb + 0u,   tb + 448u,      dW1,            IDESC_F_N128, 0);
                mma_f16_ts(tb + 0u,   tb + 448u + 8u, dW1 + 2,        IDESC_F_N128, 1);
                mma_f16_ts(tb + 256u, tb + 448u,      dW1b,           IDESC_F_N128, 0);
                mma_f16_ts(tb + 256u, tb + 448u + 8u, dW1b + 2,       IDESC_F_N128, 1);
            }
            // Z: full AZ -> finish G1 (+C0, +C1)
            BAR_SYNC_N(BAR_Z, 288);
            TCGEN05_FENCE_AFTER();
            if (elect1()) {
                mma_f16_ts(tb + 0u,   tb + 448u + 16u, dW1 + 4,       IDESC_F_N128, 1);
                mma_f16_ts(tb + 0u,   tb + 448u + 24u, dW1 + 6,       IDESC_F_N128, 1);
                TCGEN05_COMMIT(sb + SM_C0);
                mma_f16_ts(tb + 256u, tb + 448u + 16u, dW1b + 4,      IDESC_F_N128, 1);
                mma_f16_ts(tb + 256u, tb + 448u + 24u, dW1b + 6,      IDESC_F_N128, 1);
                TCGEN05_COMMIT(sb + SM_C1);
            }
            // H1A: AH1 low half -> Q0/Q1/Q2 K0-7  (D0, D1, D2)
            BAR_SYNC_N(BAR_H1A, 288);
            TCGEN05_FENCE_AFTER();
            if (elect1()) {
#pragma unroll
                for (int ks = 0; ks < 8; ks++)
                    mma_f16_ts(tb + 0u, tb + 128u + (uint32_t)(ks * 8),
                               dW2 + (uint64_t)((ks & 3) * 2 + (ks >> 2) * 2048), IDESC_F_N64, ks > 0);
#pragma unroll
                for (int ks = 0; ks < 8; ks++)
                    mma_f16_ts(tb + 64u, tb + 128u + (uint32_t)(ks * 8),
                               dW2 + (uint64_t)(512 + (ks & 3) * 2 + (ks >> 2) * 2048), IDESC_F_N64, ks > 0);
#pragma unroll
                for (int ks = 0; ks < 8; ks++)
                    mma_f16_ts(tb + 384u, tb + 128u + (uint32_t)(ks * 8),
                               dW2 + (uint64_t)(1024 + (ks & 3) * 2 + (ks >> 2) * 2048), IDESC_F_N64, ks > 0);
            }
            // H1: AH1 full -> Q0/Q1/Q2 K8-15 (+C0, +C1, +C2)
            BAR_SYNC_N(BAR_H1, 288);
            TCGEN05_FENCE_AFTER();
            if (elect1()) {
#pragma unroll
                for (int ks = 8; ks < 16; ks++)
                    mma_f16_ts(tb + 0u, tb + 128u + (uint32_t)(ks * 8),
                               dW2 + (uint64_t)((ks & 3) * 2 + (ks >> 2) * 2048), IDESC_F_N64, 1);
                TCGEN05_COMMIT(sb + SM_C0);
#pragma unroll
                for (int ks = 8; ks < 16; ks++)
                    mma_f16_ts(tb + 64u, tb + 128u + (uint32_t)(ks * 8),
                               dW2 + (uint64_t)(512 + (ks & 3) * 2 + (ks >> 2) * 2048), IDESC_F_N64, 1);
                TCGEN05_COMMIT(sb + SM_C1);
#pragma unroll
                for (int ks = 8; ks < 16; ks++)
                    mma_f16_ts(tb + 384u, tb + 128u + (uint32_t)(ks * 8),
                               dW2 + (uint64_t)(1024 + (ks & 3) * 2 + (ks >> 2) * 2048), IDESC_F_N64, 1);
                TCGEN05_COMMIT(sb + SM_C2);
            }
            // F0: D0 free (E2q0 done) -> Q3 (+C3)
            BAR_SYNC_N(BAR_F0, 288);
            TCGEN05_FENCE_AFTER();
            if (elect1()) {
#pragma unroll
                for (int ks = 0; ks < 16; ks++)
                    mma_f16_ts(tb + 0u, tb + 128u + (uint32_t)(ks * 8),
                               dW2 + (uint64_t)(1536 + (ks & 3) * 2 + (ks >> 2) * 2048), IDESC_F_N64, ks > 0);
                TCGEN05_COMMIT(sb + SM_C3);
            }
            // H2B: E2q2 done (D2 reads drained, AH2[0:96packed] written) -> G3 K0-7
            BAR_SYNC_N(BAR_H2B, 288);
            TCGEN05_FENCE_AFTER();
            if (elect1()) {
#pragma unroll
                for (int ks = 0; ks < 8; ks++)
                    mma_f16_ts(tb + 384u, tb + 256u + (uint32_t)(ks * 8),
                               dW3 + (uint64_t)((ks & 3) * 2 + (ks >> 2) * 512), IDESC_F_N64, ks > 0);
            }
            // H2: AH2 full -> finish G3 (+CA)
            BAR_SYNC_N(BAR_H2, 288);
            TCGEN05_FENCE_AFTER();
            if (elect1()) {
#pragma unroll
                for (int ks = 8; ks < 16; ks++)
                    mma_f16_ts(tb + 384u, tb + 256u + (uint32_t)(ks * 8),
                               dW3 + (uint64_t)((ks & 3) * 2 + (ks >> 2) * 512), IDESC_F_N64, 1);
                TCGEN05_COMMIT(sb + SM_CA);
            }
        }
    } else {
        // ================= worker warps (0-7) =================
        const int sp = w & 3;
        const int wg = w >> 2;
        const uint32_t warpoff = (uint32_t)sp << 21;
        const uint32_t wg64 = (uint32_t)(wg * 64);
        const uint32_t wg32 = (uint32_t)(wg * 32);
        const uint32_t wg16 = (uint32_t)(wg * 16);

        const uint32_t* bh1 = (const uint32_t*)(smem + SM_B1H);
        const uint32_t* bh2 = (const uint32_t*)(smem + SM_B2H);
        const float* b3s = (const float*)(smem + SM_B3F) + wg * 32;

        const int row = blockIdx.x * TILE_M + sp * 32 + lane;
        float zc[32], acc[32];
        {
            const float4* zp = (const float4*)(z0 + (size_t)row * DIMZ + wg * 32);
#pragma unroll
            for (int q = 0; q < 8; q++) {
                float4 v = zp[q];
                zc[4 * q] = v.x; zc[4 * q + 1] = v.y; zc[4 * q + 2] = v.z; zc[4 * q + 3] = v.w;
            }
#pragma unroll
            for (int j = 0; j < 32; j++) acc[j] = 0.0f;
        }
        // initial AZ
        {
            uint32_t o[16];
#pragma unroll
            for (int j = 0; j < 16; j++) o[j] = pack_f16x2(zc[2 * j], zc[2 * j + 1]);
            TCGEN05_ST_32X32B_X16(tb + 448u + wg16 + warpoff, o);
            TCGEN05_WAIT_ST();
            TCGEN05_FENCE_BEFORE();
            if (wg == 0) BAR_ARRIVE(BAR_Z0, 160);
            BAR_ARRIVE(BAR_Z, 288);
        }

        uint32_t pc0 = 0, pc1 = 0, pc2 = 0, pc3 = 0, pca = 0;

        for (int it = 0; it < NSTEPS * 4; ++it) {
            const int s = it & 3;

            // E1 h0: D[0,128) -> AH1[0:64packed]
            MBARRIER_WAIT_PARITY(sb + SM_C0, pc0); pc0 ^= 1u;
            TCGEN05_FENCE_AFTER();
            epi32(tb, wg64,       128u + wg32,       bh1 + wg32,      warpoff);
            epi32(tb, wg64 + 32u, 128u + wg32 + 16u, bh1 + wg32 + 16, warpoff);
            TCGEN05_FENCE_BEFORE();
            BAR_ARRIVE(BAR_H1A, 288);

            // E1 h1: D[256,384) -> AH1[64:128packed]
            MBARRIER_WAIT_PARITY(sb + SM_C1, pc1); pc1 ^= 1u;
            TCGEN05_FENCE_AFTER();
            epi32(tb, 256u + wg64,       192u + wg32,       bh1 + 64 + wg32,      warpoff);
            epi32(tb, 256u + wg64 + 32u, 192u + wg32 + 16u, bh1 + 64 + wg32 + 16, warpoff);
            TCGEN05_FENCE_BEFORE();
            BAR_ARRIVE(BAR_H1, 288);

            // E2 q0 (D0) -> AH2[0:32packed]
            MBARRIER_WAIT_PARITY(sb + SM_C0, pc0); pc0 ^= 1u;
            TCGEN05_FENCE_AFTER();
            epi32(tb, wg32, 256u + wg16, bh2 + wg16, warpoff);
            TCGEN05_FENCE_BEFORE();
            BAR_ARRIVE(BAR_F0, 288);

            // E2 q1 (D1) -> AH2[32:64packed]
            MBARRIER_WAIT_PARITY(sb + SM_C1, pc1); pc1 ^= 1u;
            TCGEN05_FENCE_AFTER();
            epi32(tb, 64u + wg32, 288u + wg16, bh2 + 32 + wg16, warpoff);

            // E2 q2 (D2=[384,448)) -> AH2[64:96packed]
            MBARRIER_WAIT_PARITY(sb + SM_C2, pc2); pc2 ^= 1u;
            TCGEN05_FENCE_AFTER();
            epi32(tb, 384u + wg32, 320u + wg16, bh2 + 64 + wg16, warpoff);
            TCGEN05_FENCE_BEFORE();
            BAR_ARRIVE(BAR_H2B, 288);

            // E2 q3 (D0) -> AH2[96:128packed]
            MBARRIER_WAIT_PARITY(sb + SM_C3, pc3); pc3 ^= 1u;
            TCGEN05_FENCE_AFTER();
            epi32(tb, wg32, 352u + wg16, bh2 + 96 + wg16, warpoff);
            TCGEN05_FENCE_BEFORE();
            BAR_ARRIVE(BAR_H2, 288);

            // E3 + RK4 update (f32 D3 at [384,448))
            MBARRIER_WAIT_PARITY(sb + SM_CA, pca); pca ^= 1u;
            TCGEN05_FENCE_AFTER();
            {
                uint32_t r[32];
                TCGEN05_LD_32X32B_X32(r, tb + 384u + wg32 + warpoff);
                TCGEN05_WAIT_LD();
                float zin[32];
                if (s == 0) {
#pragma unroll
                    for (int j = 0; j < 32; j++) {
                        float f = __uint_as_float(r[j]) + b3s[j];
                        acc[j] = f;
                        zin[j] = fmaf(0.5f * DT_F, f, zc[j]);
                    }
                } else if (s == 1) {
#pragma unroll
                    for (int j = 0; j < 32; j++) {
                        float f = __uint_as_float(r[j]) + b3s[j];
                        acc[j] = fmaf(2.0f, f, acc[j]);
                        zin[j] = fmaf(0.5f * DT_F, f, zc[j]);
                    }
                } else if (s == 2) {
#pragma unroll
                    for (int j = 0; j < 32; j++) {
                        float f = __uint_as_float(r[j]) + b3s[j];
                        acc[j] = fmaf(2.0f, f, acc[j]);
                        zin[j] = fmaf(DT_F, f, zc[j]);
                    }
                } else {
#pragma unroll
                    for (int j = 0; j < 32; j++) {
                        float f = __uint_as_float(r[j]) + b3s[j];
                        acc[j] += f;
                        zc[j] = fmaf(DT_F / 6.0f, acc[j], zc[j]);
                        zin[j] = zc[j];
                    }
                }
                uint32_t o[16];
#pragma unroll
                for (int j = 0; j < 16; j++) o[j] = pack_f16x2(zin[2 * j], zin[2 * j + 1]);
                TCGEN05_ST_32X32B_X16(tb + 448u + wg16 + warpoff, o);
                TCGEN05_WAIT_ST();
                TCGEN05_FENCE_BEFORE();
                if (wg == 0) BAR_ARRIVE(BAR_Z0, 160);
                BAR_ARRIVE(BAR_Z, 288);
            }
        }

        // ---- write result ----
        {
            float4* op = (float4*)(out + (size_t)row * DIMZ + wg * 32);
#pragma unroll
            for (int q = 0; q < 8; q++)
                op[q] = make_float4(zc[4 * q], zc[4 * q + 1], zc[4 * q + 2], zc[4 * q + 3]);
        }
    }

    __syncthreads();
    if (w == 8) TCGEN05_DEALLOC(tb, TMEM_NCOLS);
#endif  // CNF_HAS_TCGEN05
}

extern "C" void kernel_launch(void* const* d_in, const int* in_sizes, int n_in,
                              void* d_out, int out_size) {
    const float* z0 = (const float*)d_in[0];
    const float* W1 = (const float*)d_in[1];
    const float* b1 = (const float*)d_in[2];
    const float* W2 = (const float*)d_in[3];
    const float* b2 = (const float*)d_in[4];
    const float* W3 = (const float*)d_in[5];
    const float* b3 = (const float*)d_in[6];
    float* out = (float*)d_out;

    cudaFuncSetAttribute(cnf_rk4_kernel, cudaFuncAttributeMaxDynamicSharedMemorySize, SM_TOTAL);
    cnf_rk4_kernel<<<NTILES, NTHREADS, SM_TOTAL>>>(z0, W1, b1, W2, b2, W3, b3, out);
}

// round 9
// speedup vs baseline: 1.2674x; 1.0124x over previous
#include <cuda_runtime.h>
#include <cuda_fp16.h>
#include <cstdint>

#define DIMZ 64
#define HID 256
#define NBATCH 32768
#define NSTEPS 100
#define TILE_M 128
#define NTILES 256
#define NTHREADS 288   // 8 worker warps + 1 MMA warp
#define DT_F 0.01f

// tcgen05 is sm_103a arch-specific: only emit in the arch-specific pass.
#if defined(__CUDA_ARCH__)
#if defined(__CUDA_ARCH_FEAT_SM103_ALL) || \
    (defined(__CUDA_ARCH_SPECIFIC__) && (__CUDA_ARCH_SPECIFIC__ == 1030)) || \
    (defined(__CUDA_ARCH_HAS_FEATURE__) && defined(__CUDA_ARCH_FEAT_SM101_ALL))
#define CNF_HAS_TCGEN05 1
#else
#define CNF_HAS_TCGEN05 0
#endif
#else
#define CNF_HAS_TCGEN05 0
#endif

// ---- TMEM columns (480/512) ----
// [0,64)    D0   : G2 Q0, Q3 ping   (also G1h0 D low half)
// [64,128)  D1   : G2 Q1            (also G1h0 D high half)
// [128,256) AH1  : layer-1 activations f16 packed (K=256)
// [256,384) DW1  : G1h1 D (f32) --- then overwritten as AH2 (f16 packed)
// [384,448) D2   : G2 Q2 --- then reused as D3 (f32 D of GEMM3; n0=[384,416), n1=[416,448))
// [448,480) AZ   : z input f16 packed (K=64)
#define TMEM_NCOLS 512u

// ---- named HW barriers (bar0 = __syncthreads) ----
#define BAR_Z0 1    // 160: wg0 workers (128) + MMA warp (32)
#define BAR_Z 2     // 288
#define BAR_H1A 3   // 288
#define BAR_H1 4    // 288
#define BAR_H2B 5   // 288
#define BAR_H2 6    // 288
#define BAR_F0 7    // 288

// ---- SMEM byte layout ----
#define SM_TMEMPTR 0
#define SM_C0 8
#define SM_C1 16
#define SM_C2 24
#define SM_C3 32
#define SM_CA 40
#define SM_CB 48
#define SM_B1H 96       // 128 x u32 (half2 bias1 pairs)
#define SM_B2H 608      // 128 x u32 (half2 bias2 pairs)
#define SM_B3F 1120     // 64 x f32 bias3
#define SM_W1 2048      // [256 n][64 k] f16, 128B rows, SW128  (32 KB)
#define SM_W2 34816     // [256 n][256 k] f16 blocked atoms     (128 KB)
#define SM_W3 165888    // [64 n][256 k] f16 blocked atoms      (32 KB)
#define SM_TOTAL 198656

// idesc kind::f16: atype=btype=F16(0); dtype F32=(1<<4); N/8<<17; M/16<<24
#define IDESC_F_N128 0x08200010u
#define IDESC_F_N64 0x08100010u
#define IDESC_F_N32 0x08080010u

static constexpr uint64_t DESC_BASE_SW128 =
    (uint64_t(2) << 61) | (uint64_t(1) << 46) | (uint64_t(64) << 32) | (uint64_t(1) << 16);

#if CNF_HAS_TCGEN05

__device__ __forceinline__ uint32_t smem_u32(const void* p) {
    uint32_t a;
    asm("{ .reg .u64 t; cvta.to.shared.u64 t, %1; cvt.u32.u64 %0, t; }" : "=r"(a) : "l"(p));
    return a;
}
__device__ __forceinline__ uint32_t elect1() {
    uint32_t r;
    asm volatile("{ .reg .pred p; elect.sync _|p, 0xFFFFFFFF; selp.b32 %0, 1, 0, p; }" : "=r"(r));
    return r;
}
__device__ __forceinline__ uint32_t swz128(uint32_t x) { return x ^ ((x >> 3) & 0x70); }

__device__ __forceinline__ uint32_t pack_f16x2(float lo, float hi) {
    uint32_t d;
    asm("cvt.rn.f16x2.f32 %0, %1, %2;" : "=r"(d) : "f"(hi), "f"(lo));
    return d;
}
__device__ __forceinline__ uint32_t hadd2u(uint32_t a, uint32_t b) {
    uint32_t d;
    asm("add.rn.f16x2 %0, %1, %2;" : "=r"(d) : "r"(a), "r"(b));
    return d;
}
__device__ __forceinline__ uint32_t htanh2(uint32_t a) {
    uint32_t d;
    asm("tanh.approx.f16x2 %0, %1;" : "=r"(d) : "r"(a));
    return d;
}

#define TCGEN05_ALLOC(smem_addr, nCols) \
    asm volatile("tcgen05.alloc.cta_group::1.sync.aligned.shared::cta.b32 [%0], %1;" \
                 :: "r"((uint32_t)(smem_addr)), "r"((uint32_t)(nCols)) : "memory")
#define TCGEN05_DEALLOC(tmem_addr, nCols) \
    asm volatile("tcgen05.dealloc.cta_group::1.sync.aligned.b32 %0, %1;" \
                 :: "r"(tmem_addr), "r"((uint32_t)(nCols)))
#define TCGEN05_WAIT_LD() asm volatile("tcgen05.wait::ld.sync.aligned;" ::: "memory")
#define TCGEN05_WAIT_ST() asm volatile("tcgen05.wait::st.sync.aligned;" ::: "memory")
#define TCGEN05_FENCE_BEFORE() asm volatile("tcgen05.fence::before_thread_sync;" ::: "memory")
#define TCGEN05_FENCE_AFTER() asm volatile("tcgen05.fence::after_thread_sync;" ::: "memory")
#define TCGEN05_COMMIT(mbar) \
    asm volatile("tcgen05.commit.cta_group::1.mbarrier::arrive::one.shared::cluster.b64 [%0];" \
                 :: "r"((uint32_t)(mbar)) : "memory")
#define MBARRIER_INIT(mbar, count) \
    asm volatile("mbarrier.init.shared.b64 [%0], %1;" \
                 :: "r"((uint32_t)(mbar)), "r"((uint32_t)(count)) : "memory")
#define FENCE_PROXY_ASYNC() asm volatile("fence.proxy.async.shared::cta;" ::: "memory")
#define BAR_ARRIVE(id, cnt) \
    asm volatile("bar.arrive %0, %1;" :: "r"((uint32_t)(id)), "r"((uint32_t)(cnt)) : "memory")
#define BAR_SYNC_N(id, cnt) \
    asm volatile("bar.sync %0, %1;" :: "r"((uint32_t)(id)), "r"((uint32_t)(cnt)) : "memory")

#define MBARRIER_WAIT_PARITY(mbar_smem_addr, phase_parity) do { \
    uint32_t _mbar = (uint32_t)(mbar_smem_addr); \
    uint32_t _parity = (uint32_t)(phase_parity); \
    uint32_t _done; \
    asm volatile( \
        "{\n\t" \
        ".reg .pred p;\n\t" \
        "mbarrier.try_wait.parity.acquire.cta.shared::cta.b64 p, [%1], %2;\n\t" \
        "selp.b32 %0, 1, 0, p;\n\t" \
        "}" \
        : "=r"(_done) : "r"(_mbar), "r"(_parity) : "memory"); \
    if (!_done) { \
        asm volatile( \
            "{\n\t" \
            ".reg .pred P1;\n\t" \
            "WAIT_LOOP_%=:\n\t" \
            "mbarrier.try_wait.parity.acquire.cta.shared::cta.b64 P1, [%0], %1, 0x989680;\n\t" \
            "@P1 bra.uni WAIT_DONE_%=;\n\t" \
            "bra.uni WAIT_LOOP_%=;\n\t" \
            "WAIT_DONE_%=:\n\t" \
            "}" \
            :: "r"(_mbar), "r"(_parity) : "memory"); \
    } \
} while (0)

#define TCGEN05_LD_32X32B_X32(r, tmem_addr) \
    asm volatile( \
        "tcgen05.ld.sync.aligned.32x32b.x32.b32 " \
        "{%0, %1, %2, %3, %4, %5, %6, %7, " \
        " %8, %9, %10, %11, %12, %13, %14, %15, " \
        " %16, %17, %18, %19, %20, %21, %22, %23, " \
        " %24, %25, %26, %27, %28, %29, %30, %31}, [%32];" \
        : "=r"((r)[0]),  "=r"((r)[1]),  "=r"((r)[2]),  "=r"((r)[3]), \
          "=r"((r)[4]),  "=r"((r)[5]),  "=r"((r)[6]),  "=r"((r)[7]), \
          "=r"((r)[8]),  "=r"((r)[9]),  "=r"((r)[10]), "=r"((r)[11]), \
          "=r"((r)[12]), "=r"((r)[13]), "=r"((r)[14]), "=r"((r)[15]), \
          "=r"((r)[16]), "=r"((r)[17]), "=r"((r)[18]), "=r"((r)[19]), \
          "=r"((r)[20]), "=r"((r)[21]), "=r"((r)[22]), "=r"((r)[23]), \
          "=r"((r)[24]), "=r"((r)[25]), "=r"((r)[26]), "=r"((r)[27]), \
          "=r"((r)[28]), "=r"((r)[29]), "=r"((r)[30]), "=r"((r)[31]) \
        : "r"(tmem_addr))

#define TCGEN05_ST_32X32B_X16(tmem_addr, r) \
    asm volatile( \
        "tcgen05.st.sync.aligned.32x32b.x16.b32 [%0], " \
        "{%1, %2, %3, %4, %5, %6, %7, %8, " \
        " %9, %10, %11, %12, %13, %14, %15, %16};" \
        :: "r"(tmem_addr), \
           "r"((r)[0]),  "r"((r)[1]),  "r"((r)[2]),  "r"((r)[3]), \
           "r"((r)[4]),  "r"((r)[5]),  "r"((r)[6]),  "r"((r)[7]), \
           "r"((r)[8]),  "r"((r)[9]),  "r"((r)[10]), "r"((r)[11]), \
           "r"((r)[12]), "r"((r)[13]), "r"((r)[14]), "r"((r)[15]) \
        : "memory")

__device__ __forceinline__ void mma_f16_ts(uint32_t d, uint32_t a, uint64_t bdesc,
                                           uint32_t idesc, uint32_t accum) {
    asm volatile(
        "{\n\t"
        ".reg .pred p;\n\t"
        "setp.ne.u32 p, %5, 0;\n\t"
        "tcgen05.mma.cta_group::1.kind::f16 [%0], [%1], %2, %3, {%4, %4, %4, %4}, p;\n\t"
        "}"
        :: "r"(d), "r"(a), "l"(bdesc), "r"(idesc), "r"(0u), "r"(accum)
        : "memory");
}

// Single epilogue chunk: LDTM 32 f32 D cols, pack+bias+tanh, STTM 16 packed.
__device__ __forceinline__ void epi32(uint32_t tb, uint32_t dsrc, uint32_t adst,
                                      const uint32_t* bias16, uint32_t warpoff) {
    uint32_t r[32];
    TCGEN05_LD_32X32B_X32(r, tb + dsrc + warpoff);
    TCGEN05_WAIT_LD();
    uint32_t o[16];
#pragma unroll
    for (int j = 0; j < 16; j++) {
        uint32_t p = pack_f16x2(__uint_as_float(r[2 * j]), __uint_as_float(r[2 * j + 1]));
        o[j] = htanh2(hadd2u(p, bias16[j]));
    }
    TCGEN05_ST_32X32B_X16(tb + adst + warpoff, o);
    TCGEN05_WAIT_ST();
}

// Paired epilogue: issue BOTH LDTMs before waiting, then math+store both.
__device__ __forceinline__ void epi64(uint32_t tb, uint32_t dsrc0, uint32_t dsrc1,
                                      uint32_t adst0, uint32_t adst1,
                                      const uint32_t* bias0, const uint32_t* bias1,
                                      uint32_t warpoff) {
    uint32_t r0[32], r1[32];
    TCGEN05_LD_32X32B_X32(r0, tb + dsrc0 + warpoff);
    TCGEN05_LD_32X32B_X32(r1, tb + dsrc1 + warpoff);
    TCGEN05_WAIT_LD();
    uint32_t o[16];
#pragma unroll
    for (int j = 0; j < 16; j++) {
        uint32_t p = pack_f16x2(__uint_as_float(r0[2 * j]), __uint_as_float(r0[2 * j + 1]));
        o[j] = htanh2(hadd2u(p, bias0[j]));
    }
    TCGEN05_ST_32X32B_X16(tb + adst0 + warpoff, o);
#pragma unroll
    for (int j = 0; j < 16; j++) {
        uint32_t p = pack_f16x2(__uint_as_float(r1[2 * j]), __uint_as_float(r1[2 * j + 1]));
        o[j] = htanh2(hadd2u(p, bias1[j]));
    }
    TCGEN05_ST_32X32B_X16(tb + adst1 + warpoff, o);
    TCGEN05_WAIT_ST();
}

#endif  // CNF_HAS_TCGEN05

extern "C" __global__ void __launch_bounds__(NTHREADS, 1)
cnf_rk4_kernel(const float* __restrict__ z0,
               const float* __restrict__ W1, const float* __restrict__ b1,
               const float* __restrict__ W2, const float* __restrict__ b2,
               const float* __restrict__ W3, const float* __restrict__ b3,
               float* __restrict__ out) {
#if CNF_HAS_TCGEN05
    extern __shared__ char smem[];
    const uint32_t sb = smem_u32(smem);
    const int tid = threadIdx.x;
    const int w = tid >> 5;
    const int lane = tid & 31;

    if (w == 8) TCGEN05_ALLOC(sb + SM_TMEMPTR, TMEM_NCOLS);

    // ---- Weights -> f16 B-operand layouts in SMEM ----
    for (int i = tid; i < 64 * 256; i += NTHREADS) {
        int k = i >> 8, n = i & 255;
        *(__half*)(smem + SM_W1 + swz128((uint32_t)(n * 128 + k * 2))) = __float2half_rn(W1[i]);
    }
    for (int i = tid; i < 256 * 256; i += NTHREADS) {
        int k = i >> 8, n = i & 255;
        uint32_t off = (uint32_t)((((n >> 3) + (k >> 6) * 32) << 10) + ((n & 7) << 7) + ((k & 63) << 1));
        *(__half*)(smem + SM_W2 + swz128(off)) = __float2half_rn(W2[i]);
    }
    for (int i = tid; i < 256 * 64; i += NTHREADS) {
        int k = i >> 6, n = i & 63;
        uint32_t off = (uint32_t)((((n >> 3) + (k >> 6) * 8) << 10) + ((n & 7) << 7) + ((k & 63) << 1));
        *(__half*)(smem + SM_W3 + swz128(off)) = __float2half_rn(W3[i]);
    }
    for (int i = tid; i < 128; i += NTHREADS) {
        ((uint32_t*)(smem + SM_B1H))[i] = pack_f16x2(b1[2 * i], b1[2 * i + 1]);
        ((uint32_t*)(smem + SM_B2H))[i] = pack_f16x2(b2[2 * i], b2[2 * i + 1]);
    }
    for (int i = tid; i < 64; i += NTHREADS) ((float*)(smem + SM_B3F))[i] = b3[i];

    if (tid == 0) {
        MBARRIER_INIT(sb + SM_C0, 1); MBARRIER_INIT(sb + SM_C1, 1);
        MBARRIER_INIT(sb + SM_C2, 1); MBARRIER_INIT(sb + SM_C3, 1);
        MBARRIER_INIT(sb + SM_CA, 1); MBARRIER_INIT(sb + SM_CB, 1);
    }
    FENCE_PROXY_ASYNC();
    __syncthreads();

    uint32_t tb;
    asm volatile("ld.shared.b32 %0, [%1];" : "=r"(tb) : "r"(sb + SM_TMEMPTR));

    if (w == 8) {
        // ================= MMA-issue warp =================
        const uint64_t dW1 = DESC_BASE_SW128 | (((uint64_t)((sb + SM_W1) >> 4)) & 0x3FFF);
        const uint64_t dW2 = DESC_BASE_SW128 | (((uint64_t)((sb + SM_W2) >> 4)) & 0x3FFF);
        const uint64_t dW3 = DESC_BASE_SW128 | (((uint64_t)((sb + SM_W3) >> 4)) & 0x3FFF);
        const uint64_t dW1b = dW1 + 1024;
        const uint64_t dW3b = dW3 + 256;   // W3 n-half b (+4 KB)

        for (int it = 0; it < NSTEPS * 4; ++it) {
            // Z0: wg0's AZ half ready -> G1 K0-1 of both halves
            BAR_SYNC_N(BAR_Z0, 160);
            TCGEN05_FENCE_AFTER();
            if (elect1()) {
                mma_f16_ts(tb + 0u,   tb + 448u,      dW1,      IDESC_F_N128, 0);
                mma_f16_ts(tb + 0u,   tb + 448u + 8u, dW1 + 2,  IDESC_F_N128, 1);
                mma_f16_ts(tb + 256u, tb + 448u,      dW1b,     IDESC_F_N128, 0);
                mma_f16_ts(tb + 256u, tb + 448u + 8u, dW1b + 2, IDESC_F_N128, 1);
            }
            // Z: full AZ -> finish G1 (+C0, +C1)
            BAR_SYNC_N(BAR_Z, 288);
            TCGEN05_FENCE_AFTER();
            if (elect1()) {
                mma_f16_ts(tb + 0u,   tb + 448u + 16u, dW1 + 4,  IDESC_F_N128, 1);
                mma_f16_ts(tb + 0u,   tb + 448u + 24u, dW1 + 6,  IDESC_F_N128, 1);
                TCGEN05_COMMIT(sb + SM_C0);
                mma_f16_ts(tb + 256u, tb + 448u + 16u, dW1b + 4, IDESC_F_N128, 1);
                mma_f16_ts(tb + 256u, tb + 448u + 24u, dW1b + 6, IDESC_F_N128, 1);
                TCGEN05_COMMIT(sb + SM_C1);
            }
            // H1A: AH1 low half -> Q0/Q1/Q2 K0-7  (D0, D1, D2)
            BAR_SYNC_N(BAR_H1A, 288);
            TCGEN05_FENCE_AFTER();
            if (elect1()) {
#pragma unroll
                for (int ks = 0; ks < 8; ks++)
                    mma_f16_ts(tb + 0u, tb + 128u + (uint32_t)(ks * 8),
                               dW2 + (uint64_t)((ks & 3) * 2 + (ks >> 2) * 2048), IDESC_F_N64, ks > 0);
#pragma unroll
                for (int ks = 0; ks < 8; ks++)
                    mma_f16_ts(tb + 64u, tb + 128u + (uint32_t)(ks * 8),
                               dW2 + (uint64_t)(512 + (ks & 3) * 2 + (ks >> 2) * 2048), IDESC_F_N64, ks > 0);
#pragma unroll
                for (int ks = 0; ks < 8; ks++)
                    mma_f16_ts(tb + 384u, tb + 128u + (uint32_t)(ks * 8),
                               dW2 + (uint64_t)(1024 + (ks & 3) * 2 + (ks >> 2) * 2048), IDESC_F_N64, ks > 0);
            }
            // H1: AH1 full -> Q0/Q1/Q2 K8-15 (+C0, +C1, +C2)
            BAR_SYNC_N(BAR_H1, 288);
            TCGEN05_FENCE_AFTER();
            if (elect1()) {
#pragma unroll
                for (int ks = 8; ks < 16; ks++)
                    mma_f16_ts(tb + 0u, tb + 128u + (uint32_t)(ks * 8),
                               dW2 + (uint64_t)((ks & 3) * 2 + (ks >> 2) * 2048), IDESC_F_N64, 1);
                TCGEN05_COMMIT(sb + SM_C0);
#pragma unroll
                for (int ks = 8; ks < 16; ks++)
                    mma_f16_ts(tb + 64u, tb + 128u + (uint32_t)(ks * 8),
                               dW2 + (uint64_t)(512 + (ks & 3) * 2 + (ks >> 2) * 2048), IDESC_F_N64, 1);
                TCGEN05_COMMIT(sb + SM_C1);
#pragma unroll
                for (int ks = 8; ks < 16; ks++)
                    mma_f16_ts(tb + 384u, tb + 128u + (uint32_t)(ks * 8),
                               dW2 + (uint64_t)(1024 + (ks & 3) * 2 + (ks >> 2) * 2048), IDESC_F_N64, 1);
                TCGEN05_COMMIT(sb + SM_C2);
            }
            // F0: D0 reads drained (early-release from E2q0) -> Q3 (+C3)
            BAR_SYNC_N(BAR_F0, 288);
            TCGEN05_FENCE_AFTER();
            if (elect1()) {
#pragma unroll
                for (int ks = 0; ks < 16; ks++)
                    mma_f16_ts(tb + 0u, tb + 128u + (uint32_t)(ks * 8),
                               dW2 + (uint64_t)(1536 + (ks & 3) * 2 + (ks >> 2) * 2048), IDESC_F_N64, ks > 0);
                TCGEN05_COMMIT(sb + SM_C3);
            }
            // H2B: E2q2 done -> G3 n0/n1 K0-7
            BAR_SYNC_N(BAR_H2B, 288);
            TCGEN05_FENCE_AFTER();
            if (elect1()) {
#pragma unroll
                for (int ks = 0; ks < 8; ks++)
                    mma_f16_ts(tb + 384u, tb + 256u + (uint32_t)(ks * 8),
                               dW3 + (uint64_t)((ks & 3) * 2 + (ks >> 2) * 512), IDESC_F_N32, ks > 0);
#pragma unroll
                for (int ks = 0; ks < 8; ks++)
                    mma_f16_ts(tb + 416u, tb + 256u + (uint32_t)(ks * 8),
                               dW3b + (uint64_t)((ks & 3) * 2 + (ks >> 2) * 512), IDESC_F_N32, ks > 0);
            }
            // H2: AH2 full -> finish G3 n0 (+CA) then n1 (+CB)
            BAR_SYNC_N(BAR_H2, 288);
            TCGEN05_FENCE_AFTER();
            if (elect1()) {
#pragma unroll
                for (int ks = 8; ks < 16; ks++)
                    mma_f16_ts(tb + 384u, tb + 256u + (uint32_t)(ks * 8),
                               dW3 + (uint64_t)((ks & 3) * 2 + (ks >> 2) * 512), IDESC_F_N32, 1);
                TCGEN05_COMMIT(sb + SM_CA);
#pragma unroll
                for (int ks = 8; ks < 16; ks++)
                    mma_f16_ts(tb + 416u, tb + 256u + (uint32_t)(ks * 8),
                               dW3b + (uint64_t)((ks & 3) * 2 + (ks >> 2) * 512), IDESC_F_N32, 1);
                TCGEN05_COMMIT(sb + SM_CB);
            }
        }
    } else {
        // ================= worker warps (0-7) =================
        const int sp = w & 3;
        const int wg = w >> 2;
        const uint32_t warpoff = (uint32_t)sp << 21;
        const uint32_t wg64 = (uint32_t)(wg * 64);
        const uint32_t wg32 = (uint32_t)(wg * 32);
        const uint32_t wg16 = (uint32_t)(wg * 16);

        const uint32_t* bh1 = (const uint32_t*)(smem + SM_B1H);
        const uint32_t* bh2 = (const uint32_t*)(smem + SM_B2H);
        const float* b3s = (const float*)(smem + SM_B3F) + wg * 32;
        const uint32_t myCbar = (wg == 0) ? (sb + SM_CA) : (sb + SM_CB);

        const int row = blockIdx.x * TILE_M + sp * 32 + lane;
        float zc[32], acc[32];
        {
            const float4* zp = (const float4*)(z0 + (size_t)row * DIMZ + wg * 32);
#pragma unroll
            for (int q = 0; q < 8; q++) {
                float4 v = zp[q];
                zc[4 * q] = v.x; zc[4 * q + 1] = v.y; zc[4 * q + 2] = v.z; zc[4 * q + 3] = v.w;
            }
#pragma unroll
            for (int j = 0; j < 32; j++) acc[j] = 0.0f;
        }
        // initial AZ
        {
            uint32_t o[16];
#pragma unroll
            for (int j = 0; j < 16; j++) o[j] = pack_f16x2(zc[2 * j], zc[2 * j + 1]);
            TCGEN05_ST_32X32B_X16(tb + 448u + wg16 + warpoff, o);
            TCGEN05_WAIT_ST();
            TCGEN05_FENCE_BEFORE();
            if (wg == 0) BAR_ARRIVE(BAR_Z0, 160);
            BAR_ARRIVE(BAR_Z, 288);
        }

        uint32_t pc0 = 0, pc1 = 0, pc2 = 0, pc3 = 0, pcz = 0;

        for (int it = 0; it < NSTEPS * 4; ++it) {
            const int s = it & 3;

            // E1 h0: D[0,128) -> AH1[0:64packed]  (paired LDTM)
            MBARRIER_WAIT_PARITY(sb + SM_C0, pc0); pc0 ^= 1u;
            TCGEN05_FENCE_AFTER();
            epi64(tb, wg64, wg64 + 32u, 128u + wg32, 128u + wg32 + 16u,
                  bh1 + wg32, bh1 + wg32 + 16, warpoff);
            TCGEN05_FENCE_BEFORE();
            BAR_ARRIVE(BAR_H1A, 288);

            // E1 h1: D[256,384) -> AH1[64:128packed]  (paired LDTM)
            MBARRIER_WAIT_PARITY(sb + SM_C1, pc1); pc1 ^= 1u;
            TCGEN05_FENCE_AFTER();
            epi64(tb, 256u + wg64, 256u + wg64 + 32u, 192u + wg32, 192u + wg32 + 16u,
                  bh1 + 64 + wg32, bh1 + 64 + wg32 + 16, warpoff);
            TCGEN05_FENCE_BEFORE();
            BAR_ARRIVE(BAR_H1, 288);

            // E2 q0 (D0) -> AH2[0:32packed]; release F0 right after LDTM drains
            MBARRIER_WAIT_PARITY(sb + SM_C0, pc0); pc0 ^= 1u;
            TCGEN05_FENCE_AFTER();
            {
                uint32_t r[32];
                TCGEN05_LD_32X32B_X32(r, tb + wg32 + warpoff);
                TCGEN05_WAIT_LD();
                TCGEN05_FENCE_BEFORE();
                BAR_ARRIVE(BAR_F0, 288);    // D0 reads done; Q3 may start
                uint32_t o[16];
#pragma unroll
                for (int j = 0; j < 16; j++) {
                    uint32_t p = pack_f16x2(__uint_as_float(r[2 * j]), __uint_as_float(r[2 * j + 1]));
                    o[j] = htanh2(hadd2u(p, bh2[wg16 + j]));
                }
                TCGEN05_ST_32X32B_X16(tb + 256u + wg16 + warpoff, o);
                TCGEN05_WAIT_ST();
            }

            // E2 q1 (D1) -> AH2[32:64packed]
            MBARRIER_WAIT_PARITY(sb + SM_C1, pc1); pc1 ^= 1u;
            TCGEN05_FENCE_AFTER();
            epi32(tb, 64u + wg32, 288u + wg16, bh2 + 32 + wg16, warpoff);

            // E2 q2 (D2=[384,448)) -> AH2[64:96packed]
            MBARRIER_WAIT_PARITY(sb + SM_C2, pc2); pc2 ^= 1u;
            TCGEN05_FENCE_AFTER();
            epi32(tb, 384u + wg32, 320u + wg16, bh2 + 64 + wg16, warpoff);
            TCGEN05_FENCE_BEFORE();
            BAR_ARRIVE(BAR_H2B, 288);

            // E2 q3 (D0) -> AH2[96:128packed]
            MBARRIER_WAIT_PARITY(sb + SM_C3, pc3); pc3 ^= 1u;
            TCGEN05_FENCE_AFTER();
            epi32(tb, wg32, 352u + wg16, bh2 + 96 + wg16, warpoff);
            TCGEN05_FENCE_BEFORE();
            BAR_ARRIVE(BAR_H2, 288);

            // E3 + RK4 update: wg0 waits CA (n0 = feats 0-31), wg1 waits CB
            MBARRIER_WAIT_PARITY(myCbar, pcz); pcz ^= 1u;
            TCGEN05_FENCE_AFTER();
            {
                uint32_t r[32];
                TCGEN05_LD_32X32B_X32(r, tb + 384u + wg32 + warpoff);
                TCGEN05_WAIT_LD();
                float zin[32];
                if (s == 0) {
#pragma unroll
                    for (int j = 0; j < 32; j++) {
                        float f = __uint_as_float(r[j]) + b3s[j];
                        acc[j] = f;
                        zin[j] = fmaf(0.5f * DT_F, f, zc[j]);
                    }
                } else if (s == 1) {
#pragma unroll
                    for (int j = 0; j < 32; j++) {
                        float f = __uint_as_float(r[j]) + b3s[j];
                        acc[j] = fmaf(2.0f, f, acc[j]);
                        zin[j] = fmaf(0.5f * DT_F, f, zc[j]);
                    }
                } else if (s == 2) {
#pragma unroll
                    for (int j = 0; j < 32; j++) {
                        float f = __uint_as_float(r[j]) + b3s[j];
                        acc[j] = fmaf(2.0f, f, acc[j]);
                        zin[j] = fmaf(DT_F, f, zc[j]);
                    }
                } else {
#pragma unroll
                    for (int j = 0; j < 32; j++) {
                        float f = __uint_as_float(r[j]) + b3s[j];
                        acc[j] += f;
                        zc[j] = fmaf(DT_F / 6.0f, acc[j], zc[j]);
                        zin[j] = zc[j];
                    }
                }
                uint32_t o[16];
#pragma unroll
                for (int j = 0; j < 16; j++) o[j] = pack_f16x2(zin[2 * j], zin[2 * j + 1]);
                TCGEN05_ST_32X32B_X16(tb + 448u + wg16 + warpoff, o);
                TCGEN05_WAIT_ST();
                TCGEN05_FENCE_BEFORE();
                if (wg == 0) BAR_ARRIVE(BAR_Z0, 160);
                BAR_ARRIVE(BAR_Z, 288);
            }
        }

        // ---- write result ----
        {
            float4* op = (float4*)(out + (size_t)row * DIMZ + wg * 32);
#pragma unroll
            for (int q = 0; q < 8; q++)
                op[q] = make_float4(zc[4 * q], zc[4 * q + 1], zc[4 * q + 2], zc[4 * q + 3]);
        }
    }

    __syncthreads();
    if (w == 8) TCGEN05_DEALLOC(tb, TMEM_NCOLS);
#endif  // CNF_HAS_TCGEN05
}

extern "C" void kernel_launch(void* const* d_in, const int* in_sizes, int n_in,
                              void* d_out, int out_size) {
    const float* z0 = (const float*)d_in[0];
    const float* W1 = (const float*)d_in[1];
    const float* b1 = (const float*)d_in[2];
    const float* W2 = (const float*)d_in[3];
    const float* b2 = (const float*)d_in[4];
    const float* W3 = (const float*)d_in[5];
    const float* b3 = (const float*)d_in[6];
    float* out = (float*)d_out;

    cudaFuncSetAttribute(cnf_rk4_kernel, cudaFuncAttributeMaxDynamicSharedMemorySize, SM_TOTAL);
    cnf_rk4_kernel<<<NTILES, NTHREADS, SM_TOTAL>>>(z0, W1, b1, W2, b2, W3, b3, out);
}